// round 1
// baseline (speedup 1.0000x reference)
#include <cuda_runtime.h>
#include <math.h>

// Problem dims
#define LL 1024
#define BB 4
#define DD 1024
#define HH 16
#define HDIM 64
#define BHEADS 64
#define DFF 4096
#define MROWS 4096            // L*B
#define QKV_N 3072            // 3*D
#define ROW_STRIDE 12288      // B*3D (stride between consecutive l for fixed batch in qkv)

// Scratch (allocation-free: __device__ globals)
__device__ float g_h   [(size_t)MROWS * DD];
__device__ float g_qkv [(size_t)MROWS * QKV_N];
__device__ float g_P   [(size_t)BHEADS * LL * LL];
__device__ float g_attn[(size_t)MROWS * DD];
__device__ float g_x1  [(size_t)MROWS * DD];
__device__ float g_h2  [(size_t)MROWS * DD];
__device__ float g_ffn [(size_t)MROWS * DFF];

// ---------------- LayerNorm: one block per row of 1024 ----------------
__global__ __launch_bounds__(256) void layernorm_k(
    const float* __restrict__ in, const float* __restrict__ w,
    const float* __restrict__ b, float* __restrict__ out)
{
    int row = blockIdx.x;
    int tid = threadIdx.x;
    const float* r = in + (size_t)row * DD;
    float4 v = *(const float4*)(r + tid * 4);
    float s  = v.x + v.y + v.z + v.w;
    float sq = v.x * v.x + v.y * v.y + v.z * v.z + v.w * v.w;
    #pragma unroll
    for (int o = 16; o > 0; o >>= 1) {
        s  += __shfl_xor_sync(0xffffffffu, s,  o);
        sq += __shfl_xor_sync(0xffffffffu, sq, o);
    }
    __shared__ float ss[8], ssq[8];
    int warp = tid >> 5, lane = tid & 31;
    if (lane == 0) { ss[warp] = s; ssq[warp] = sq; }
    __syncthreads();
    float ts = 0.f, tsq = 0.f;
    #pragma unroll
    for (int i = 0; i < 8; i++) { ts += ss[i]; tsq += ssq[i]; }
    float mu  = ts * (1.f / 1024.f);
    float var = tsq * (1.f / 1024.f) - mu * mu;
    float inv = rsqrtf(var + 1e-5f);
    float4 wv = *(const float4*)(w + tid * 4);
    float4 bv = *(const float4*)(b + tid * 4);
    float4 o4;
    o4.x = (v.x - mu) * inv * wv.x + bv.x;
    o4.y = (v.y - mu) * inv * wv.y + bv.y;
    o4.z = (v.z - mu) * inv * wv.z + bv.z;
    o4.w = (v.w - mu) * inv * wv.w + bv.w;
    *(float4*)(out + (size_t)row * DD + tid * 4) = o4;
}

__device__ __forceinline__ float gelu_exact(float x) {
    return 0.5f * x * (1.0f + erff(x * 0.70710678118654752f));
}

// ---------------- Tiled GEMM: C[M,N] = A[M,K] @ B[N,K]^T + bias (+epilogue)
// EPI: 0 = bias only, 1 = gelu(bias+..), 2 = residual add
template<int EPI>
__global__ __launch_bounds__(256) void gemm_nt(
    const float* __restrict__ A, const float* __restrict__ Bm,
    const float* __restrict__ bias, const float* __restrict__ res,
    float* __restrict__ C, int N, int K)
{
    __shared__ float As[16][132];
    __shared__ float Bs[16][132];
    int m0 = blockIdx.y << 7, n0 = blockIdx.x << 7;
    int tid = threadIdx.x, tx = tid & 15, ty = tid >> 4;
    float acc[8][8] = {};
    for (int k0 = 0; k0 < K; k0 += 16) {
        #pragma unroll
        for (int t = 0; t < 2; t++) {
            int idx = tid + (t << 8);          // 0..511
            int row = idx >> 2, c4 = (idx & 3) << 2;
            float4 v = *(const float4*)(A  + (size_t)(m0 + row) * K + k0 + c4);
            As[c4][row] = v.x; As[c4+1][row] = v.y; As[c4+2][row] = v.z; As[c4+3][row] = v.w;
            float4 u = *(const float4*)(Bm + (size_t)(n0 + row) * K + k0 + c4);
            Bs[c4][row] = u.x; Bs[c4+1][row] = u.y; Bs[c4+2][row] = u.z; Bs[c4+3][row] = u.w;
        }
        __syncthreads();
        #pragma unroll
        for (int kk = 0; kk < 16; kk++) {
            float a[8], b[8];
            #pragma unroll
            for (int i = 0; i < 8; i++) a[i] = As[kk][(ty << 3) + i];
            #pragma unroll
            for (int j = 0; j < 8; j++) b[j] = Bs[kk][(tx << 3) + j];
            #pragma unroll
            for (int i = 0; i < 8; i++)
                #pragma unroll
                for (int j = 0; j < 8; j++)
                    acc[i][j] = fmaf(a[i], b[j], acc[i][j]);
        }
        __syncthreads();
    }
    #pragma unroll
    for (int i = 0; i < 8; i++) {
        int m = m0 + (ty << 3) + i;
        #pragma unroll
        for (int j4 = 0; j4 < 8; j4 += 4) {
            int n = n0 + (tx << 3) + j4;
            float4 bb = *(const float4*)(bias + n);
            float4 c;
            c.x = acc[i][j4+0] + bb.x;
            c.y = acc[i][j4+1] + bb.y;
            c.z = acc[i][j4+2] + bb.z;
            c.w = acc[i][j4+3] + bb.w;
            if (EPI == 1) {
                c.x = gelu_exact(c.x); c.y = gelu_exact(c.y);
                c.z = gelu_exact(c.z); c.w = gelu_exact(c.w);
            } else if (EPI == 2) {
                float4 rr = *(const float4*)(res + (size_t)m * N + n);
                c.x += rr.x; c.y += rr.y; c.z += rr.z; c.w += rr.w;
            }
            *(float4*)(C + (size_t)m * N + n) = c;
        }
    }
}

// ---------------- Attention scores: t = QK^T/8 + edge -> edge_out -----
__global__ __launch_bounds__(256) void attn_scores(
    const float* __restrict__ qkv, const float* __restrict__ edge,
    float* __restrict__ edge_out)
{
    __shared__ float Qs[16][132];
    __shared__ float Ks[16][132];
    int bz = blockIdx.z;                 // head index bh = batch*H + h
    int batch = bz >> 4, h = bz & 15;
    int qoff = batch * QKV_N + h * HDIM;
    int koff = qoff + DD;
    int i0 = blockIdx.y << 7, j0 = blockIdx.x << 7;
    int tid = threadIdx.x, tx = tid & 15, ty = tid >> 4;
    float acc[8][8] = {};
    for (int k0 = 0; k0 < HDIM; k0 += 16) {
        #pragma unroll
        for (int t = 0; t < 2; t++) {
            int idx = tid + (t << 8);
            int row = idx >> 2, c4 = (idx & 3) << 2;
            float4 v = *(const float4*)(qkv + (size_t)(i0 + row) * ROW_STRIDE + qoff + k0 + c4);
            Qs[c4][row] = v.x; Qs[c4+1][row] = v.y; Qs[c4+2][row] = v.z; Qs[c4+3][row] = v.w;
            float4 u = *(const float4*)(qkv + (size_t)(j0 + row) * ROW_STRIDE + koff + k0 + c4);
            Ks[c4][row] = u.x; Ks[c4+1][row] = u.y; Ks[c4+2][row] = u.z; Ks[c4+3][row] = u.w;
        }
        __syncthreads();
        #pragma unroll
        for (int kk = 0; kk < 16; kk++) {
            float a[8], b[8];
            #pragma unroll
            for (int i = 0; i < 8; i++) a[i] = Qs[kk][(ty << 3) + i];
            #pragma unroll
            for (int j = 0; j < 8; j++) b[j] = Ks[kk][(tx << 3) + j];
            #pragma unroll
            for (int i = 0; i < 8; i++)
                #pragma unroll
                for (int j = 0; j < 8; j++)
                    acc[i][j] = fmaf(a[i], b[j], acc[i][j]);
        }
        __syncthreads();
    }
    size_t base = ((size_t)bz << 20);
    #pragma unroll
    for (int i = 0; i < 8; i++) {
        int ii = i0 + (ty << 3) + i;
        #pragma unroll
        for (int j4 = 0; j4 < 8; j4 += 4) {
            int jj = j0 + (tx << 3) + j4;
            size_t off = base + ((size_t)ii << 10) + jj;
            float4 e = *(const float4*)(edge + off);
            float4 c;
            c.x = acc[i][j4+0] * 0.125f + e.x;
            c.y = acc[i][j4+1] * 0.125f + e.y;
            c.z = acc[i][j4+2] * 0.125f + e.z;
            c.w = acc[i][j4+3] * 0.125f + e.w;
            *(float4*)(edge_out + off) = c;
        }
    }
}

// ---------------- Row softmax: P = softmax(t) over last dim (1024) ----
__global__ __launch_bounds__(128) void softmax_rows(
    const float* __restrict__ t, float* __restrict__ P)
{
    size_t row = blockIdx.x;
    const float* r = t + (row << 10);
    float* p = P + (row << 10);
    int tid = threadIdx.x;
    float4 v0 = *(const float4*)(r + tid * 8);
    float4 v1 = *(const float4*)(r + tid * 8 + 4);
    float mx = fmaxf(fmaxf(fmaxf(v0.x, v0.y), fmaxf(v0.z, v0.w)),
                     fmaxf(fmaxf(v1.x, v1.y), fmaxf(v1.z, v1.w)));
    #pragma unroll
    for (int o = 16; o > 0; o >>= 1) mx = fmaxf(mx, __shfl_xor_sync(0xffffffffu, mx, o));
    __shared__ float sm[4];
    __shared__ float sssum[4];
    int warp = tid >> 5, lane = tid & 31;
    if (lane == 0) sm[warp] = mx;
    __syncthreads();
    float m = fmaxf(fmaxf(sm[0], sm[1]), fmaxf(sm[2], sm[3]));
    float e0 = __expf(v0.x - m), e1 = __expf(v0.y - m), e2 = __expf(v0.z - m), e3 = __expf(v0.w - m);
    float e4 = __expf(v1.x - m), e5 = __expf(v1.y - m), e6 = __expf(v1.z - m), e7 = __expf(v1.w - m);
    float s = e0 + e1 + e2 + e3 + e4 + e5 + e6 + e7;
    #pragma unroll
    for (int o = 16; o > 0; o >>= 1) s += __shfl_xor_sync(0xffffffffu, s, o);
    if (lane == 0) sssum[warp] = s;
    __syncthreads();
    float tot = sssum[0] + sssum[1] + sssum[2] + sssum[3];
    float inv = 1.0f / tot;
    float4 w0 = make_float4(e0 * inv, e1 * inv, e2 * inv, e3 * inv);
    float4 w1 = make_float4(e4 * inv, e5 * inv, e6 * inv, e7 * inv);
    *(float4*)(p + tid * 8)     = w0;
    *(float4*)(p + tid * 8 + 4) = w1;
}

// ---------------- PV: out[bh,i,:] = P[bh,i,:] @ V[bh,:,:] ------------
__global__ __launch_bounds__(256) void attn_pv(
    const float* __restrict__ P, const float* __restrict__ qkv,
    float* __restrict__ out)
{
    __shared__ float Ps[32][132];
    __shared__ float Vs[32][72];
    int bz = blockIdx.y;                  // head
    int batch = bz >> 4, h = bz & 15;
    int voff = batch * QKV_N + 2 * DD + h * HDIM;
    int i0 = blockIdx.x << 7;
    int tid = threadIdx.x, tx = tid & 15, ty = tid >> 4;
    float acc[8][4] = {};
    size_t pbase = ((size_t)bz << 20);
    for (int k0 = 0; k0 < LL; k0 += 32) {
        #pragma unroll
        for (int t = 0; t < 4; t++) {
            int idx = tid + (t << 8);        // 0..1023
            int row = idx >> 3, c4 = (idx & 7) << 2;
            float4 v = *(const float4*)(P + pbase + ((size_t)(i0 + row) << 10) + k0 + c4);
            Ps[c4][row] = v.x; Ps[c4+1][row] = v.y; Ps[c4+2][row] = v.z; Ps[c4+3][row] = v.w;
        }
        #pragma unroll
        for (int t = 0; t < 2; t++) {
            int idx = tid + (t << 8);        // 0..511
            int row = idx >> 4, c4 = (idx & 15) << 2;
            float4 v = *(const float4*)(qkv + (size_t)(k0 + row) * ROW_STRIDE + voff + c4);
            *(float4*)&Vs[row][c4] = v;
        }
        __syncthreads();
        #pragma unroll
        for (int kk = 0; kk < 32; kk++) {
            float a[8], b[4];
            #pragma unroll
            for (int i = 0; i < 8; i++) a[i] = Ps[kk][(ty << 3) + i];
            #pragma unroll
            for (int j = 0; j < 4; j++) b[j] = Vs[kk][(tx << 2) + j];
            #pragma unroll
            for (int i = 0; i < 8; i++)
                #pragma unroll
                for (int j = 0; j < 4; j++)
                    acc[i][j] = fmaf(a[i], b[j], acc[i][j]);
        }
        __syncthreads();
    }
    #pragma unroll
    for (int i = 0; i < 8; i++) {
        int l = i0 + (ty << 3) + i;
        int row = l * BB + batch;            // [L,B,D] flattened row
        float4 c = make_float4(acc[i][0], acc[i][1], acc[i][2], acc[i][3]);
        *(float4*)(out + (size_t)row * DD + h * HDIM + (tx << 2)) = c;
    }
}

extern "C" void kernel_launch(void* const* d_in, const int* in_sizes, int n_in,
                              void* d_out, int out_size)
{
    const float* x    = (const float*)d_in[0];
    const float* edge = (const float*)d_in[1];
    const float* Wqkv = (const float*)d_in[2];
    const float* bqkv = (const float*)d_in[3];
    const float* Wo   = (const float*)d_in[4];
    const float* bo   = (const float*)d_in[5];
    const float* W1   = (const float*)d_in[6];
    const float* b1   = (const float*)d_in[7];
    const float* W2   = (const float*)d_in[8];
    const float* b2   = (const float*)d_in[9];
    const float* n1w  = (const float*)d_in[10];
    const float* n1b  = (const float*)d_in[11];
    const float* n2w  = (const float*)d_in[12];
    const float* n2b  = (const float*)d_in[13];

    float* out_x    = (float*)d_out;
    float* edge_out = out_x + (size_t)MROWS * DD;   // x first, then edge_out

    float *h, *qkv, *P, *attn, *x1, *h2, *ffn;
    cudaGetSymbolAddress((void**)&h,    g_h);
    cudaGetSymbolAddress((void**)&qkv,  g_qkv);
    cudaGetSymbolAddress((void**)&P,    g_P);
    cudaGetSymbolAddress((void**)&attn, g_attn);
    cudaGetSymbolAddress((void**)&x1,   g_x1);
    cudaGetSymbolAddress((void**)&h2,   g_h2);
    cudaGetSymbolAddress((void**)&ffn,  g_ffn);

    // 1) h = LN1(x)
    layernorm_k<<<MROWS, 256>>>(x, n1w, n1b, h);
    // 2) qkv = h @ Wqkv^T + bqkv        [4096, 3072]
    gemm_nt<0><<<dim3(QKV_N / 128, MROWS / 128), 256>>>(h, Wqkv, bqkv, nullptr, qkv, QKV_N, DD);
    // 3) edge_out = QK^T/8 + edge       [64, 1024, 1024]
    attn_scores<<<dim3(8, 8, BHEADS), 256>>>(qkv, edge, edge_out);
    // 4) P = softmax(edge_out)
    softmax_rows<<<BHEADS * LL, 128>>>(edge_out, P);
    // 5) attn = P @ V                   -> [L,B,D] layout
    attn_pv<<<dim3(8, BHEADS), 256>>>(P, qkv, attn);
    // 6) x1 = x + attn @ Wo^T + bo
    gemm_nt<2><<<dim3(DD / 128, MROWS / 128), 256>>>(attn, Wo, bo, x, x1, DD, DD);
    // 7) h2 = LN2(x1)
    layernorm_k<<<MROWS, 256>>>(x1, n2w, n2b, h2);
    // 8) ffn = gelu(h2 @ W1^T + b1)     [4096, 4096]
    gemm_nt<1><<<dim3(DFF / 128, MROWS / 128), 256>>>(h2, W1, b1, nullptr, ffn, DFF, DD);
    // 9) out_x = x1 + ffn @ W2^T + b2
    gemm_nt<2><<<dim3(DD / 128, MROWS / 128), 256>>>(ffn, W2, b2, x1, out_x, DD, DFF);
}

// round 4
// speedup vs baseline: 2.0779x; 2.0779x over previous
#include <cuda_runtime.h>
#include <math.h>
#include <stdint.h>

// Problem dims
#define LL 1024
#define BB 4
#define DD 1024
#define HH 16
#define HDIM 64
#define BHEADS 64
#define DFF 4096
#define MROWS 4096            // L*B
#define QKV_N 3072            // 3*D
#define ROW_STRIDE 12288      // B*3D

// Scratch (allocation-free: __device__ globals)
__device__ float g_h   [(size_t)MROWS * DD];
__device__ float g_qkv [(size_t)MROWS * QKV_N];
__device__ float g_P   [(size_t)BHEADS * LL * LL];
__device__ float g_attn[(size_t)MROWS * DD];
__device__ float g_x1  [(size_t)MROWS * DD];
__device__ float g_h2  [(size_t)MROWS * DD];
__device__ float g_ffn [(size_t)MROWS * DFF];

// ---------------- helpers ----------------
__device__ __forceinline__ uint32_t f2tf32(float x) {
    uint32_t r;
    asm("cvt.rna.tf32.f32 %0, %1;" : "=r"(r) : "f"(x));
    return r;
}

__device__ __forceinline__ void mma_tf32(float c[4],
    uint32_t a0, uint32_t a1, uint32_t a2, uint32_t a3,
    uint32_t b0, uint32_t b1)
{
    asm volatile(
        "mma.sync.aligned.m16n8k8.row.col.f32.tf32.tf32.f32 "
        "{%0,%1,%2,%3}, {%4,%5,%6,%7}, {%8,%9}, {%0,%1,%2,%3};\n"
        : "+f"(c[0]), "+f"(c[1]), "+f"(c[2]), "+f"(c[3])
        : "r"(a0), "r"(a1), "r"(a2), "r"(a3), "r"(b0), "r"(b1));
}

__device__ __forceinline__ float gelu_exact(float x) {
    return 0.5f * x * (1.0f + erff(x * 0.70710678118654752f));
}

// ---------------- LayerNorm ----------------
__global__ __launch_bounds__(256) void layernorm_k(
    const float* __restrict__ in, const float* __restrict__ w,
    const float* __restrict__ b, float* __restrict__ out)
{
    int row = blockIdx.x;
    int tid = threadIdx.x;
    const float* r = in + (size_t)row * DD;
    float4 v = *(const float4*)(r + tid * 4);
    float s  = v.x + v.y + v.z + v.w;
    float sq = v.x * v.x + v.y * v.y + v.z * v.z + v.w * v.w;
    #pragma unroll
    for (int o = 16; o > 0; o >>= 1) {
        s  += __shfl_xor_sync(0xffffffffu, s,  o);
        sq += __shfl_xor_sync(0xffffffffu, sq, o);
    }
    __shared__ float ss[8], ssq[8];
    int warp = tid >> 5, lane = tid & 31;
    if (lane == 0) { ss[warp] = s; ssq[warp] = sq; }
    __syncthreads();
    float ts = 0.f, tsq = 0.f;
    #pragma unroll
    for (int i = 0; i < 8; i++) { ts += ss[i]; tsq += ssq[i]; }
    float mu  = ts * (1.f / 1024.f);
    float var = tsq * (1.f / 1024.f) - mu * mu;
    float inv = rsqrtf(var + 1e-5f);
    float4 wv = *(const float4*)(w + tid * 4);
    float4 bv = *(const float4*)(b + tid * 4);
    float4 o4;
    o4.x = (v.x - mu) * inv * wv.x + bv.x;
    o4.y = (v.y - mu) * inv * wv.y + bv.y;
    o4.z = (v.z - mu) * inv * wv.z + bv.z;
    o4.w = (v.w - mu) * inv * wv.w + bv.w;
    *(float4*)(out + (size_t)row * DD + tid * 4) = o4;
}

// ---------------- tf32 tensor-core GEMM: C[M,N] = A[M,K] @ B[N,K]^T ----
// 128x128 block tile, BK=16, 8 warps in 4x2, warp tile 32x64 (2x8 m16n8 mmas)
// EPI: 0 bias, 1 bias+gelu, 2 bias+residual
template<int EPI>
__global__ __launch_bounds__(256) void gemm_tc(
    const float* __restrict__ A, const float* __restrict__ Bm,
    const float* __restrict__ bias, const float* __restrict__ res,
    float* __restrict__ C, int N, int K)
{
    __shared__ uint32_t As[128][20];
    __shared__ uint32_t Bs[128][20];
    int m0 = blockIdx.y << 7, n0 = blockIdx.x << 7;
    int tid = threadIdx.x;
    int warp = tid >> 5, lane = tid & 31;
    int gid = lane >> 2, tig = lane & 3;
    int wm = (warp & 3) << 5, wn = (warp >> 2) << 6;
    float acc[2][8][4] = {};
    for (int k0 = 0; k0 < K; k0 += 16) {
        #pragma unroll
        for (int t = 0; t < 2; t++) {
            int idx = tid + (t << 8);
            int row = idx >> 2, c4 = (idx & 3) << 2;
            float4 v = *(const float4*)(A  + (size_t)(m0 + row) * K + k0 + c4);
            uint4 u = make_uint4(f2tf32(v.x), f2tf32(v.y), f2tf32(v.z), f2tf32(v.w));
            *(uint4*)&As[row][c4] = u;
            float4 w = *(const float4*)(Bm + (size_t)(n0 + row) * K + k0 + c4);
            uint4 uw = make_uint4(f2tf32(w.x), f2tf32(w.y), f2tf32(w.z), f2tf32(w.w));
            *(uint4*)&Bs[row][c4] = uw;
        }
        __syncthreads();
        #pragma unroll
        for (int ks = 0; ks < 16; ks += 8) {
            uint32_t a[2][4], b[8][2];
            #pragma unroll
            for (int mi = 0; mi < 2; mi++) {
                int m = wm + (mi << 4) + gid;
                a[mi][0] = As[m][ks + tig];
                a[mi][1] = As[m + 8][ks + tig];
                a[mi][2] = As[m][ks + tig + 4];
                a[mi][3] = As[m + 8][ks + tig + 4];
            }
            #pragma unroll
            for (int nj = 0; nj < 8; nj++) {
                int n = wn + (nj << 3) + gid;
                b[nj][0] = Bs[n][ks + tig];
                b[nj][1] = Bs[n][ks + tig + 4];
            }
            #pragma unroll
            for (int mi = 0; mi < 2; mi++)
                #pragma unroll
                for (int nj = 0; nj < 8; nj++)
                    mma_tf32(acc[mi][nj], a[mi][0], a[mi][1], a[mi][2], a[mi][3],
                             b[nj][0], b[nj][1]);
        }
        __syncthreads();
    }
    #pragma unroll
    for (int mi = 0; mi < 2; mi++) {
        int m = m0 + wm + (mi << 4) + gid;
        #pragma unroll
        for (int nj = 0; nj < 8; nj++) {
            int n = n0 + wn + (nj << 3) + (tig << 1);
            float2 bb = *(const float2*)(bias + n);
            float c0 = acc[mi][nj][0] + bb.x;
            float c1 = acc[mi][nj][1] + bb.y;
            float c2 = acc[mi][nj][2] + bb.x;
            float c3 = acc[mi][nj][3] + bb.y;
            if (EPI == 1) {
                c0 = gelu_exact(c0); c1 = gelu_exact(c1);
                c2 = gelu_exact(c2); c3 = gelu_exact(c3);
            } else if (EPI == 2) {
                float2 r0 = *(const float2*)(res + (size_t)m * N + n);
                float2 r1 = *(const float2*)(res + (size_t)(m + 8) * N + n);
                c0 += r0.x; c1 += r0.y; c2 += r1.x; c3 += r1.y;
            }
            *(float2*)(C + (size_t)m * N + n)       = make_float2(c0, c1);
            *(float2*)(C + (size_t)(m + 8) * N + n) = make_float2(c2, c3);
        }
    }
}

// ---------------- Attention scores (tf32): edge_out = QK^T/8 + edge ----
__global__ __launch_bounds__(256) void attn_scores_tc(
    const float* __restrict__ qkv, const float* __restrict__ edge,
    float* __restrict__ edge_out)
{
    __shared__ uint32_t As[128][20];
    __shared__ uint32_t Bs[128][20];
    int bz = blockIdx.z;
    int batch = bz >> 4, h = bz & 15;
    int qoff = batch * QKV_N + h * HDIM;
    int koff = qoff + DD;
    int i0 = blockIdx.y << 7, j0 = blockIdx.x << 7;
    int tid = threadIdx.x;
    int warp = tid >> 5, lane = tid & 31;
    int gid = lane >> 2, tig = lane & 3;
    int wm = (warp & 3) << 5, wn = (warp >> 2) << 6;
    float acc[2][8][4] = {};
    for (int k0 = 0; k0 < HDIM; k0 += 16) {
        #pragma unroll
        for (int t = 0; t < 2; t++) {
            int idx = tid + (t << 8);
            int row = idx >> 2, c4 = (idx & 3) << 2;
            float4 v = *(const float4*)(qkv + (size_t)(i0 + row) * ROW_STRIDE + qoff + k0 + c4);
            *(uint4*)&As[row][c4] = make_uint4(f2tf32(v.x), f2tf32(v.y), f2tf32(v.z), f2tf32(v.w));
            float4 w = *(const float4*)(qkv + (size_t)(j0 + row) * ROW_STRIDE + koff + k0 + c4);
            *(uint4*)&Bs[row][c4] = make_uint4(f2tf32(w.x), f2tf32(w.y), f2tf32(w.z), f2tf32(w.w));
        }
        __syncthreads();
        #pragma unroll
        for (int ks = 0; ks < 16; ks += 8) {
            uint32_t a[2][4], b[8][2];
            #pragma unroll
            for (int mi = 0; mi < 2; mi++) {
                int m = wm + (mi << 4) + gid;
                a[mi][0] = As[m][ks + tig];
                a[mi][1] = As[m + 8][ks + tig];
                a[mi][2] = As[m][ks + tig + 4];
                a[mi][3] = As[m + 8][ks + tig + 4];
            }
            #pragma unroll
            for (int nj = 0; nj < 8; nj++) {
                int n = wn + (nj << 3) + gid;
                b[nj][0] = Bs[n][ks + tig];
                b[nj][1] = Bs[n][ks + tig + 4];
            }
            #pragma unroll
            for (int mi = 0; mi < 2; mi++)
                #pragma unroll
                for (int nj = 0; nj < 8; nj++)
                    mma_tf32(acc[mi][nj], a[mi][0], a[mi][1], a[mi][2], a[mi][3],
                             b[nj][0], b[nj][1]);
        }
        __syncthreads();
    }
    size_t base = ((size_t)bz << 20);
    #pragma unroll
    for (int mi = 0; mi < 2; mi++) {
        int ii = i0 + wm + (mi << 4) + gid;
        #pragma unroll
        for (int nj = 0; nj < 8; nj++) {
            int jj = j0 + wn + (nj << 3) + (tig << 1);
            size_t off0 = base + ((size_t)ii << 10) + jj;
            size_t off1 = base + ((size_t)(ii + 8) << 10) + jj;
            float2 e0 = *(const float2*)(edge + off0);
            float2 e1 = *(const float2*)(edge + off1);
            *(float2*)(edge_out + off0) = make_float2(acc[mi][nj][0] * 0.125f + e0.x,
                                                      acc[mi][nj][1] * 0.125f + e0.y);
            *(float2*)(edge_out + off1) = make_float2(acc[mi][nj][2] * 0.125f + e1.x,
                                                      acc[mi][nj][3] * 0.125f + e1.y);
        }
    }
}

// ---------------- Row softmax ----------------
__global__ __launch_bounds__(128) void softmax_rows(
    const float* __restrict__ t, float* __restrict__ P)
{
    size_t row = blockIdx.x;
    const float* r = t + (row << 10);
    float* p = P + (row << 10);
    int tid = threadIdx.x;
    float4 v0 = *(const float4*)(r + tid * 8);
    float4 v1 = *(const float4*)(r + tid * 8 + 4);
    float mx = fmaxf(fmaxf(fmaxf(v0.x, v0.y), fmaxf(v0.z, v0.w)),
                     fmaxf(fmaxf(v1.x, v1.y), fmaxf(v1.z, v1.w)));
    #pragma unroll
    for (int o = 16; o > 0; o >>= 1) mx = fmaxf(mx, __shfl_xor_sync(0xffffffffu, mx, o));
    __shared__ float sm[4];
    __shared__ float sssum[4];
    int warp = tid >> 5, lane = tid & 31;
    if (lane == 0) sm[warp] = mx;
    __syncthreads();
    float m = fmaxf(fmaxf(sm[0], sm[1]), fmaxf(sm[2], sm[3]));
    float e0 = __expf(v0.x - m), e1 = __expf(v0.y - m), e2 = __expf(v0.z - m), e3 = __expf(v0.w - m);
    float e4 = __expf(v1.x - m), e5 = __expf(v1.y - m), e6 = __expf(v1.z - m), e7 = __expf(v1.w - m);
    float s = e0 + e1 + e2 + e3 + e4 + e5 + e6 + e7;
    #pragma unroll
    for (int o = 16; o > 0; o >>= 1) s += __shfl_xor_sync(0xffffffffu, s, o);
    if (lane == 0) sssum[warp] = s;
    __syncthreads();
    float tot = sssum[0] + sssum[1] + sssum[2] + sssum[3];
    float inv = 1.0f / tot;
    *(float4*)(p + tid * 8)     = make_float4(e0 * inv, e1 * inv, e2 * inv, e3 * inv);
    *(float4*)(p + tid * 8 + 4) = make_float4(e4 * inv, e5 * inv, e6 * inv, e7 * inv);
}

// ---------------- PV (tf32): out[l*B+batch, h*64+n] = P[bh] @ V[bh] ----
// BM=128, BN=64, BK=32; 8 warps along M, warp tile 16x64
__global__ __launch_bounds__(256) void attn_pv_tc(
    const float* __restrict__ P, const float* __restrict__ qkv,
    float* __restrict__ out)
{
    __shared__ uint32_t As[128][36];
    __shared__ uint32_t Bs[32][72];
    int bz = blockIdx.y;
    int batch = bz >> 4, h = bz & 15;
    int voff = batch * QKV_N + 2 * DD + h * HDIM;
    int i0 = blockIdx.x << 7;
    int tid = threadIdx.x;
    int warp = tid >> 5, lane = tid & 31;
    int gid = lane >> 2, tig = lane & 3;
    int wm = warp << 4;
    float acc[8][4] = {};
    size_t pbase = ((size_t)bz << 20);
    for (int k0 = 0; k0 < LL; k0 += 32) {
        #pragma unroll
        for (int t = 0; t < 4; t++) {
            int idx = tid + (t << 8);
            int row = idx >> 3, c4 = (idx & 7) << 2;
            float4 v = *(const float4*)(P + pbase + ((size_t)(i0 + row) << 10) + k0 + c4);
            *(uint4*)&As[row][c4] = make_uint4(f2tf32(v.x), f2tf32(v.y), f2tf32(v.z), f2tf32(v.w));
        }
        #pragma unroll
        for (int t = 0; t < 2; t++) {
            int idx = tid + (t << 8);
            int row = idx >> 4, c4 = (idx & 15) << 2;
            float4 v = *(const float4*)(qkv + (size_t)(k0 + row) * ROW_STRIDE + voff + c4);
            *(uint4*)&Bs[row][c4] = make_uint4(f2tf32(v.x), f2tf32(v.y), f2tf32(v.z), f2tf32(v.w));
        }
        __syncthreads();
        #pragma unroll
        for (int ks = 0; ks < 32; ks += 8) {
            uint32_t a[4], b[8][2];
            int m = wm + gid;
            a[0] = As[m][ks + tig];
            a[1] = As[m + 8][ks + tig];
            a[2] = As[m][ks + tig + 4];
            a[3] = As[m + 8][ks + tig + 4];
            #pragma unroll
            for (int nj = 0; nj < 8; nj++) {
                int n = (nj << 3) + gid;
                b[nj][0] = Bs[ks + tig][n];
                b[nj][1] = Bs[ks + tig + 4][n];
            }
            #pragma unroll
            for (int nj = 0; nj < 8; nj++)
                mma_tf32(acc[nj], a[0], a[1], a[2], a[3], b[nj][0], b[nj][1]);
        }
        __syncthreads();
    }
    #pragma unroll
    for (int nj = 0; nj < 8; nj++) {
        int l0 = i0 + wm + gid;
        int col = h * HDIM + (nj << 3) + (tig << 1);
        int row0 = l0 * BB + batch;
        int row1 = (l0 + 8) * BB + batch;
        *(float2*)(out + (size_t)row0 * DD + col) = make_float2(acc[nj][0], acc[nj][1]);
        *(float2*)(out + (size_t)row1 * DD + col) = make_float2(acc[nj][2], acc[nj][3]);
    }
}

extern "C" void kernel_launch(void* const* d_in, const int* in_sizes, int n_in,
                              void* d_out, int out_size)
{
    const float* x    = (const float*)d_in[0];
    const float* edge = (const float*)d_in[1];
    const float* Wqkv = (const float*)d_in[2];
    const float* bqkv = (const float*)d_in[3];
    const float* Wo   = (const float*)d_in[4];
    const float* bo   = (const float*)d_in[5];
    const float* W1   = (const float*)d_in[6];
    const float* b1   = (const float*)d_in[7];
    const float* W2   = (const float*)d_in[8];
    const float* b2   = (const float*)d_in[9];
    const float* n1w  = (const float*)d_in[10];
    const float* n1b  = (const float*)d_in[11];
    const float* n2w  = (const float*)d_in[12];
    const float* n2b  = (const float*)d_in[13];

    float* out_x    = (float*)d_out;
    float* edge_out = out_x + (size_t)MROWS * DD;

    float *h, *qkv, *P, *attn, *x1, *h2, *ffn;
    cudaGetSymbolAddress((void**)&h,    g_h);
    cudaGetSymbolAddress((void**)&qkv,  g_qkv);
    cudaGetSymbolAddress((void**)&P,    g_P);
    cudaGetSymbolAddress((void**)&attn, g_attn);
    cudaGetSymbolAddress((void**)&x1,   g_x1);
    cudaGetSymbolAddress((void**)&h2,   g_h2);
    cudaGetSymbolAddress((void**)&ffn,  g_ffn);

    // 1) h = LN1(x)
    layernorm_k<<<MROWS, 256>>>(x, n1w, n1b, h);
    // 2) qkv = h @ Wqkv^T + bqkv
    gemm_tc<0><<<dim3(QKV_N / 128, MROWS / 128), 256>>>(h, Wqkv, bqkv, nullptr, qkv, QKV_N, DD);
    // 3) edge_out = QK^T/8 + edge
    attn_scores_tc<<<dim3(8, 8, BHEADS), 256>>>(qkv, edge, edge_out);
    // 4) P = softmax(edge_out)
    softmax_rows<<<BHEADS * LL, 128>>>(edge_out, P);
    // 5) attn = P @ V
    attn_pv_tc<<<dim3(8, BHEADS), 256>>>(P, qkv, attn);
    // 6) x1 = x + attn @ Wo^T + bo
    gemm_tc<2><<<dim3(DD / 128, MROWS / 128), 256>>>(attn, Wo, bo, x, x1, DD, DD);
    // 7) h2 = LN2(x1)
    layernorm_k<<<MROWS, 256>>>(x1, n2w, n2b, h2);
    // 8) ffn = gelu(h2 @ W1^T + b1)
    gemm_tc<1><<<dim3(DFF / 128, MROWS / 128), 256>>>(h2, W1, b1, nullptr, ffn, DFF, DD);
    // 9) out_x = x1 + ffn @ W2^T + b2
    gemm_tc<2><<<dim3(DD / 128, MROWS / 128), 256>>>(ffn, W2, b2, x1, out_x, DD, DFF);
}

// round 9
// speedup vs baseline: 2.6514x; 1.2760x over previous
#include <cuda_runtime.h>
#include <math.h>
#include <stdint.h>

// Problem dims
#define LL 1024
#define BB 4
#define DD 1024
#define HH 16
#define HDIM 64
#define BHEADS 64
#define DFF 4096
#define MROWS 4096            // L*B
#define QKV_N 3072            // 3*D
#define ROW_STRIDE 12288      // B*3D

// Scratch (allocation-free: __device__ globals)
__device__ float g_h   [(size_t)MROWS * DD];
__device__ float g_qkv [(size_t)MROWS * QKV_N];
__device__ float g_P   [(size_t)BHEADS * LL * LL];
__device__ float g_attn[(size_t)MROWS * DD];
__device__ float g_x1  [(size_t)MROWS * DD];
__device__ float g_h2  [(size_t)MROWS * DD];
__device__ float g_ffn [(size_t)MROWS * DFF];

// ---------------- helpers ----------------
__device__ __forceinline__ uint32_t f2tf32(float x) {
    uint32_t r;
    asm("cvt.rna.tf32.f32 %0, %1;" : "=r"(r) : "f"(x));
    return r;
}

__device__ __forceinline__ void mma_tf32(float c[4],
    uint32_t a0, uint32_t a1, uint32_t a2, uint32_t a3,
    uint32_t b0, uint32_t b1)
{
    asm volatile(
        "mma.sync.aligned.m16n8k8.row.col.f32.tf32.tf32.f32 "
        "{%0,%1,%2,%3}, {%4,%5,%6,%7}, {%8,%9}, {%0,%1,%2,%3};\n"
        : "+f"(c[0]), "+f"(c[1]), "+f"(c[2]), "+f"(c[3])
        : "r"(a0), "r"(a1), "r"(a2), "r"(a3), "r"(b0), "r"(b1));
}

__device__ __forceinline__ float gelu_exact(float x) {
    return 0.5f * x * (1.0f + erff(x * 0.70710678118654752f));
}

__device__ __forceinline__ void cp_async16(uint32_t smem_dst, const void* gptr) {
    asm volatile("cp.async.ca.shared.global [%0], [%1], 16;\n"
                 :: "r"(smem_dst), "l"(gptr));
}
__device__ __forceinline__ void cp_commit() {
    asm volatile("cp.async.commit_group;\n");
}
template<int N>
__device__ __forceinline__ void cp_wait() {
    asm volatile("cp.async.wait_group %0;\n" :: "n"(N));
}

// ---------------- LayerNorm ----------------
__global__ __launch_bounds__(256) void layernorm_k(
    const float* __restrict__ in, const float* __restrict__ w,
    const float* __restrict__ b, float* __restrict__ out)
{
    int row = blockIdx.x;
    int tid = threadIdx.x;
    const float* r = in + (size_t)row * DD;
    float4 v = *(const float4*)(r + tid * 4);
    float s  = v.x + v.y + v.z + v.w;
    float sq = v.x * v.x + v.y * v.y + v.z * v.z + v.w * v.w;
    #pragma unroll
    for (int o = 16; o > 0; o >>= 1) {
        s  += __shfl_xor_sync(0xffffffffu, s,  o);
        sq += __shfl_xor_sync(0xffffffffu, sq, o);
    }
    __shared__ float ss[8], ssq[8];
    int warp = tid >> 5, lane = tid & 31;
    if (lane == 0) { ss[warp] = s; ssq[warp] = sq; }
    __syncthreads();
    float ts = 0.f, tsq = 0.f;
    #pragma unroll
    for (int i = 0; i < 8; i++) { ts += ss[i]; tsq += ssq[i]; }
    float mu  = ts * (1.f / 1024.f);
    float var = tsq * (1.f / 1024.f) - mu * mu;
    float inv = rsqrtf(var + 1e-5f);
    float4 wv = *(const float4*)(w + tid * 4);
    float4 bv = *(const float4*)(b + tid * 4);
    float4 o4;
    o4.x = (v.x - mu) * inv * wv.x + bv.x;
    o4.y = (v.y - mu) * inv * wv.y + bv.y;
    o4.z = (v.z - mu) * inv * wv.z + bv.z;
    o4.w = (v.w - mu) * inv * wv.w + bv.w;
    *(float4*)(out + (size_t)row * DD + tid * 4) = o4;
}

// ---------------- tf32 tensor-core GEMM, 2-stage cp.async pipeline ------
// C[M,N] = A[M,K] @ B[N,K]^T (+bias/gelu/residual)
// 128x128 block tile, BK=32, 8 warps 4x2, warp tile 32x64.
// Shared: float, stride 36 (conflict-free fragment loads: (4*row+k)%32 bijective)
#define GPAD 36
#define GSTG (128 * GPAD)

template<int EPI>
__global__ __launch_bounds__(256) void gemm_tc(
    const float* __restrict__ A, const float* __restrict__ Bm,
    const float* __restrict__ bias, const float* __restrict__ res,
    float* __restrict__ C, int N, int K)
{
    extern __shared__ float smem_g[];
    float* Asm = smem_g;                 // [2][128][GPAD]
    float* Bsm = smem_g + 2 * GSTG;      // [2][128][GPAD]

    int m0 = blockIdx.y << 7, n0 = blockIdx.x << 7;
    int tid = threadIdx.x;
    int warp = tid >> 5, lane = tid & 31;
    int gid = lane >> 2, tig = lane & 3;
    int wm = (warp & 3) << 5, wn = (warp >> 2) << 6;

    // global copy coords: 8 threads/row, 4 row-groups of 32
    int lrow = tid >> 3;              // 0..31
    int lcol = (tid & 7) << 2;        // 0,4,..,28
    const float* Ag = A  + (size_t)(m0 + lrow) * K + lcol;
    const float* Bg = Bm + (size_t)(n0 + lrow) * K + lcol;

    int nt = K >> 5;

    // prologue: tile 0 -> stage 0
    {
        uint32_t da = (uint32_t)__cvta_generic_to_shared(Asm + lrow * GPAD + lcol);
        uint32_t db = (uint32_t)__cvta_generic_to_shared(Bsm + lrow * GPAD + lcol);
        #pragma unroll
        for (int r = 0; r < 4; r++) {
            cp_async16(da + r * 32 * GPAD * 4, Ag + (size_t)(r * 32) * K);
            cp_async16(db + r * 32 * GPAD * 4, Bg + (size_t)(r * 32) * K);
        }
        cp_commit();
    }

    float acc[2][8][4] = {};

    for (int kt = 0; kt < nt; kt++) {
        if (kt + 1 < nt) {
            int st = (kt + 1) & 1;
            uint32_t da = (uint32_t)__cvta_generic_to_shared(Asm + st * GSTG + lrow * GPAD + lcol);
            uint32_t db = (uint32_t)__cvta_generic_to_shared(Bsm + st * GSTG + lrow * GPAD + lcol);
            const float* Ags = Ag + (size_t)(kt + 1) * 32;
            const float* Bgs = Bg + (size_t)(kt + 1) * 32;
            #pragma unroll
            for (int r = 0; r < 4; r++) {
                cp_async16(da + r * 32 * GPAD * 4, Ags + (size_t)(r * 32) * K);
                cp_async16(db + r * 32 * GPAD * 4, Bgs + (size_t)(r * 32) * K);
            }
            cp_commit();
            cp_wait<1>();
        } else {
            cp_wait<0>();
        }
        __syncthreads();

        const float* As = Asm + (kt & 1) * GSTG;
        const float* Bs = Bsm + (kt & 1) * GSTG;

        #pragma unroll
        for (int ks = 0; ks < 32; ks += 8) {
            uint32_t a[2][4], b[8][2];
            #pragma unroll
            for (int mi = 0; mi < 2; mi++) {
                int m = wm + (mi << 4) + gid;
                a[mi][0] = f2tf32(As[m * GPAD + ks + tig]);
                a[mi][1] = f2tf32(As[(m + 8) * GPAD + ks + tig]);
                a[mi][2] = f2tf32(As[m * GPAD + ks + tig + 4]);
                a[mi][3] = f2tf32(As[(m + 8) * GPAD + ks + tig + 4]);
            }
            #pragma unroll
            for (int nj = 0; nj < 8; nj++) {
                int n = wn + (nj << 3) + gid;
                b[nj][0] = f2tf32(Bs[n * GPAD + ks + tig]);
                b[nj][1] = f2tf32(Bs[n * GPAD + ks + tig + 4]);
            }
            #pragma unroll
            for (int mi = 0; mi < 2; mi++)
                #pragma unroll
                for (int nj = 0; nj < 8; nj++)
                    mma_tf32(acc[mi][nj], a[mi][0], a[mi][1], a[mi][2], a[mi][3],
                             b[nj][0], b[nj][1]);
        }
        __syncthreads();
    }

    #pragma unroll
    for (int mi = 0; mi < 2; mi++) {
        int m = m0 + wm + (mi << 4) + gid;
        #pragma unroll
        for (int nj = 0; nj < 8; nj++) {
            int n = n0 + wn + (nj << 3) + (tig << 1);
            float2 bb = *(const float2*)(bias + n);
            float c0 = acc[mi][nj][0] + bb.x;
            float c1 = acc[mi][nj][1] + bb.y;
            float c2 = acc[mi][nj][2] + bb.x;
            float c3 = acc[mi][nj][3] + bb.y;
            if (EPI == 1) {
                c0 = gelu_exact(c0); c1 = gelu_exact(c1);
                c2 = gelu_exact(c2); c3 = gelu_exact(c3);
            } else if (EPI == 2) {
                float2 r0 = *(const float2*)(res + (size_t)m * N + n);
                float2 r1 = *(const float2*)(res + (size_t)(m + 8) * N + n);
                c0 += r0.x; c1 += r0.y; c2 += r1.x; c3 += r1.y;
            }
            *(float2*)(C + (size_t)m * N + n)       = make_float2(c0, c1);
            *(float2*)(C + (size_t)(m + 8) * N + n) = make_float2(c2, c3);
        }
    }
}

#define GEMM_SMEM (4 * GSTG * (int)sizeof(float))   // 73728 bytes

// ---------------- Attention scores (tf32): edge_out = QK^T/8 + edge ----
__global__ __launch_bounds__(256) void attn_scores_tc(
    const float* __restrict__ qkv, const float* __restrict__ edge,
    float* __restrict__ edge_out)
{
    __shared__ uint32_t As[128][20];
    __shared__ uint32_t Bs[128][20];
    int bz = blockIdx.z;
    int batch = bz >> 4, h = bz & 15;
    int qoff = batch * QKV_N + h * HDIM;
    int koff = qoff + DD;
    int i0 = blockIdx.y << 7, j0 = blockIdx.x << 7;
    int tid = threadIdx.x;
    int warp = tid >> 5, lane = tid & 31;
    int gid = lane >> 2, tig = lane & 3;
    int wm = (warp & 3) << 5, wn = (warp >> 2) << 6;
    float acc[2][8][4] = {};
    for (int k0 = 0; k0 < HDIM; k0 += 16) {
        #pragma unroll
        for (int t = 0; t < 2; t++) {
            int idx = tid + (t << 8);
            int row = idx >> 2, c4 = (idx & 3) << 2;
            float4 v = *(const float4*)(qkv + (size_t)(i0 + row) * ROW_STRIDE + qoff + k0 + c4);
            *(uint4*)&As[row][c4] = make_uint4(f2tf32(v.x), f2tf32(v.y), f2tf32(v.z), f2tf32(v.w));
            float4 w = *(const float4*)(qkv + (size_t)(j0 + row) * ROW_STRIDE + koff + k0 + c4);
            *(uint4*)&Bs[row][c4] = make_uint4(f2tf32(w.x), f2tf32(w.y), f2tf32(w.z), f2tf32(w.w));
        }
        __syncthreads();
        #pragma unroll
        for (int ks = 0; ks < 16; ks += 8) {
            uint32_t a[2][4], b[8][2];
            #pragma unroll
            for (int mi = 0; mi < 2; mi++) {
                int m = wm + (mi << 4) + gid;
                a[mi][0] = As[m][ks + tig];
                a[mi][1] = As[m + 8][ks + tig];
                a[mi][2] = As[m][ks + tig + 4];
                a[mi][3] = As[m + 8][ks + tig + 4];
            }
            #pragma unroll
            for (int nj = 0; nj < 8; nj++) {
                int n = wn + (nj << 3) + gid;
                b[nj][0] = Bs[n][ks + tig];
                b[nj][1] = Bs[n][ks + tig + 4];
            }
            #pragma unroll
            for (int mi = 0; mi < 2; mi++)
                #pragma unroll
                for (int nj = 0; nj < 8; nj++)
                    mma_tf32(acc[mi][nj], a[mi][0], a[mi][1], a[mi][2], a[mi][3],
                             b[nj][0], b[nj][1]);
        }
        __syncthreads();
    }
    size_t base = ((size_t)bz << 20);
    #pragma unroll
    for (int mi = 0; mi < 2; mi++) {
        int ii = i0 + wm + (mi << 4) + gid;
        #pragma unroll
        for (int nj = 0; nj < 8; nj++) {
            int jj = j0 + wn + (nj << 3) + (tig << 1);
            size_t off0 = base + ((size_t)ii << 10) + jj;
            size_t off1 = base + ((size_t)(ii + 8) << 10) + jj;
            float2 e0 = *(const float2*)(edge + off0);
            float2 e1 = *(const float2*)(edge + off1);
            *(float2*)(edge_out + off0) = make_float2(acc[mi][nj][0] * 0.125f + e0.x,
                                                      acc[mi][nj][1] * 0.125f + e0.y);
            *(float2*)(edge_out + off1) = make_float2(acc[mi][nj][2] * 0.125f + e1.x,
                                                      acc[mi][nj][3] * 0.125f + e1.y);
        }
    }
}

// ---------------- Row softmax ----------------
__global__ __launch_bounds__(128) void softmax_rows(
    const float* __restrict__ t, float* __restrict__ P)
{
    size_t row = blockIdx.x;
    const float* r = t + (row << 10);
    float* p = P + (row << 10);
    int tid = threadIdx.x;
    float4 v0 = *(const float4*)(r + tid * 8);
    float4 v1 = *(const float4*)(r + tid * 8 + 4);
    float mx = fmaxf(fmaxf(fmaxf(v0.x, v0.y), fmaxf(v0.z, v0.w)),
                     fmaxf(fmaxf(v1.x, v1.y), fmaxf(v1.z, v1.w)));
    #pragma unroll
    for (int o = 16; o > 0; o >>= 1) mx = fmaxf(mx, __shfl_xor_sync(0xffffffffu, mx, o));
    __shared__ float sm[4];
    __shared__ float sssum[4];
    int warp = tid >> 5, lane = tid & 31;
    if (lane == 0) sm[warp] = mx;
    __syncthreads();
    float m = fmaxf(fmaxf(sm[0], sm[1]), fmaxf(sm[2], sm[3]));
    float e0 = __expf(v0.x - m), e1 = __expf(v0.y - m), e2 = __expf(v0.z - m), e3 = __expf(v0.w - m);
    float e4 = __expf(v1.x - m), e5 = __expf(v1.y - m), e6 = __expf(v1.z - m), e7 = __expf(v1.w - m);
    float s = e0 + e1 + e2 + e3 + e4 + e5 + e6 + e7;
    #pragma unroll
    for (int o = 16; o > 0; o >>= 1) s += __shfl_xor_sync(0xffffffffu, s, o);
    if (lane == 0) sssum[warp] = s;
    __syncthreads();
    float tot = sssum[0] + sssum[1] + sssum[2] + sssum[3];
    float inv = 1.0f / tot;
    *(float4*)(p + tid * 8)     = make_float4(e0 * inv, e1 * inv, e2 * inv, e3 * inv);
    *(float4*)(p + tid * 8 + 4) = make_float4(e4 * inv, e5 * inv, e6 * inv, e7 * inv);
}

// ---------------- PV (tf32) ----------------
__global__ __launch_bounds__(256) void attn_pv_tc(
    const float* __restrict__ P, const float* __restrict__ qkv,
    float* __restrict__ out)
{
    __shared__ uint32_t As[128][36];
    __shared__ uint32_t Bs[32][72];
    int bz = blockIdx.y;
    int batch = bz >> 4, h = bz & 15;
    int voff = batch * QKV_N + 2 * DD + h * HDIM;
    int i0 = blockIdx.x << 7;
    int tid = threadIdx.x;
    int warp = tid >> 5, lane = tid & 31;
    int gid = lane >> 2, tig = lane & 3;
    int wm = warp << 4;
    float acc[8][4] = {};
    size_t pbase = ((size_t)bz << 20);
    for (int k0 = 0; k0 < LL; k0 += 32) {
        #pragma unroll
        for (int t = 0; t < 4; t++) {
            int idx = tid + (t << 8);
            int row = idx >> 3, c4 = (idx & 7) << 2;
            float4 v = *(const float4*)(P + pbase + ((size_t)(i0 + row) << 10) + k0 + c4);
            *(uint4*)&As[row][c4] = make_uint4(f2tf32(v.x), f2tf32(v.y), f2tf32(v.z), f2tf32(v.w));
        }
        #pragma unroll
        for (int t = 0; t < 2; t++) {
            int idx = tid + (t << 8);
            int row = idx >> 4, c4 = (idx & 15) << 2;
            float4 v = *(const float4*)(qkv + (size_t)(k0 + row) * ROW_STRIDE + voff + c4);
            *(uint4*)&Bs[row][c4] = make_uint4(f2tf32(v.x), f2tf32(v.y), f2tf32(v.z), f2tf32(v.w));
        }
        __syncthreads();
        #pragma unroll
        for (int ks = 0; ks < 32; ks += 8) {
            uint32_t a[4], b[8][2];
            int m = wm + gid;
            a[0] = As[m][ks + tig];
            a[1] = As[m + 8][ks + tig];
            a[2] = As[m][ks + tig + 4];
            a[3] = As[m + 8][ks + tig + 4];
            #pragma unroll
            for (int nj = 0; nj < 8; nj++) {
                int n = (nj << 3) + gid;
                b[nj][0] = Bs[ks + tig][n];
                b[nj][1] = Bs[ks + tig + 4][n];
            }
            #pragma unroll
            for (int nj = 0; nj < 8; nj++)
                mma_tf32(acc[nj], a[0], a[1], a[2], a[3], b[nj][0], b[nj][1]);
        }
        __syncthreads();
    }
    #pragma unroll
    for (int nj = 0; nj < 8; nj++) {
        int l0 = i0 + wm + gid;
        int col = h * HDIM + (nj << 3) + (tig << 1);
        int row0 = l0 * BB + batch;
        int row1 = (l0 + 8) * BB + batch;
        *(float2*)(out + (size_t)row0 * DD + col) = make_float2(acc[nj][0], acc[nj][1]);
        *(float2*)(out + (size_t)row1 * DD + col) = make_float2(acc[nj][2], acc[nj][3]);
    }
}

extern "C" void kernel_launch(void* const* d_in, const int* in_sizes, int n_in,
                              void* d_out, int out_size)
{
    const float* x    = (const float*)d_in[0];
    const float* edge = (const float*)d_in[1];
    const float* Wqkv = (const float*)d_in[2];
    const float* bqkv = (const float*)d_in[3];
    const float* Wo   = (const float*)d_in[4];
    const float* bo   = (const float*)d_in[5];
    const float* W1   = (const float*)d_in[6];
    const float* b1   = (const float*)d_in[7];
    const float* W2   = (const float*)d_in[8];
    const float* b2   = (const float*)d_in[9];
    const float* n1w  = (const float*)d_in[10];
    const float* n1b  = (const float*)d_in[11];
    const float* n2w  = (const float*)d_in[12];
    const float* n2b  = (const float*)d_in[13];

    float* out_x    = (float*)d_out;
    float* edge_out = out_x + (size_t)MROWS * DD;

    float *h, *qkv, *P, *attn, *x1, *h2, *ffn;
    cudaGetSymbolAddress((void**)&h,    g_h);
    cudaGetSymbolAddress((void**)&qkv,  g_qkv);
    cudaGetSymbolAddress((void**)&P,    g_P);
    cudaGetSymbolAddress((void**)&attn, g_attn);
    cudaGetSymbolAddress((void**)&x1,   g_x1);
    cudaGetSymbolAddress((void**)&h2,   g_h2);
    cudaGetSymbolAddress((void**)&ffn,  g_ffn);

    // Allow 72KB dynamic smem for the pipelined GEMMs (non-stream op; capture-safe)
    cudaFuncSetAttribute(gemm_tc<0>, cudaFuncAttributeMaxDynamicSharedMemorySize, GEMM_SMEM);
    cudaFuncSetAttribute(gemm_tc<1>, cudaFuncAttributeMaxDynamicSharedMemorySize, GEMM_SMEM);
    cudaFuncSetAttribute(gemm_tc<2>, cudaFuncAttributeMaxDynamicSharedMemorySize, GEMM_SMEM);

    // 1) h = LN1(x)
    layernorm_k<<<MROWS, 256>>>(x, n1w, n1b, h);
    // 2) qkv = h @ Wqkv^T + bqkv
    gemm_tc<0><<<dim3(QKV_N / 128, MROWS / 128), 256, GEMM_SMEM>>>(h, Wqkv, bqkv, nullptr, qkv, QKV_N, DD);
    // 3) edge_out = QK^T/8 + edge
    attn_scores_tc<<<dim3(8, 8, BHEADS), 256>>>(qkv, edge, edge_out);
    // 4) P = softmax(edge_out)
    softmax_rows<<<BHEADS * LL, 128>>>(edge_out, P);
    // 5) attn = P @ V
    attn_pv_tc<<<dim3(8, BHEADS), 256>>>(P, qkv, attn);
    // 6) x1 = x + attn @ Wo^T + bo
    gemm_tc<2><<<dim3(DD / 128, MROWS / 128), 256, GEMM_SMEM>>>(attn, Wo, bo, x, x1, DD, DD);
    // 7) h2 = LN2(x1)
    layernorm_k<<<MROWS, 256>>>(x1, n2w, n2b, h2);
    // 8) ffn = gelu(h2 @ W1^T + b1)
    gemm_tc<1><<<dim3(DFF / 128, MROWS / 128), 256, GEMM_SMEM>>>(h2, W1, b1, nullptr, ffn, DFF, DD);
    // 9) out_x = x1 + ffn @ W2^T + b2
    gemm_tc<2><<<dim3(DD / 128, MROWS / 128), 256, GEMM_SMEM>>>(ffn, W2, b2, x1, out_x, DD, DFF);
}

// round 10
// speedup vs baseline: 2.8396x; 1.0710x over previous
#include <cuda_runtime.h>
#include <math.h>
#include <stdint.h>

// Problem dims
#define LL 1024
#define BB 4
#define DD 1024
#define HH 16
#define HDIM 64
#define BHEADS 64
#define DFF 4096
#define MROWS 4096            // L*B
#define QKV_N 3072            // 3*D
#define ROW_STRIDE 12288      // B*3D

// Scratch (allocation-free: __device__ globals)
__device__ float g_h   [(size_t)MROWS * DD];
__device__ float g_qkv [(size_t)MROWS * QKV_N];
__device__ float g_P   [(size_t)BHEADS * LL * LL];
__device__ float g_attn[(size_t)MROWS * DD];
__device__ float g_x1  [(size_t)MROWS * DD];
__device__ float g_h2  [(size_t)MROWS * DD];
__device__ float g_ffn [(size_t)MROWS * DFF];
// tf32-pre-rounded weight copies
__device__ float g_wqkv[(size_t)QKV_N * DD];
__device__ float g_wo  [(size_t)DD * DD];
__device__ float g_w1  [(size_t)DFF * DD];
__device__ float g_w2  [(size_t)DD * DFF];

// ---------------- helpers ----------------
__device__ __forceinline__ uint32_t f2tf32(float x) {
    uint32_t r;
    asm("cvt.rna.tf32.f32 %0, %1;" : "=r"(r) : "f"(x));
    return r;
}
__device__ __forceinline__ float round_tf32(float x) {
    return __uint_as_float(f2tf32(x));
}

__device__ __forceinline__ void mma_tf32(float c[4],
    uint32_t a0, uint32_t a1, uint32_t a2, uint32_t a3,
    uint32_t b0, uint32_t b1)
{
    asm volatile(
        "mma.sync.aligned.m16n8k8.row.col.f32.tf32.tf32.f32 "
        "{%0,%1,%2,%3}, {%4,%5,%6,%7}, {%8,%9}, {%0,%1,%2,%3};\n"
        : "+f"(c[0]), "+f"(c[1]), "+f"(c[2]), "+f"(c[3])
        : "r"(a0), "r"(a1), "r"(a2), "r"(a3), "r"(b0), "r"(b1));
}

__device__ __forceinline__ float gelu_exact(float x) {
    return 0.5f * x * (1.0f + erff(x * 0.70710678118654752f));
}

__device__ __forceinline__ void cp_async16(uint32_t smem_dst, const void* gptr) {
    asm volatile("cp.async.ca.shared.global [%0], [%1], 16;\n"
                 :: "r"(smem_dst), "l"(gptr));
}
__device__ __forceinline__ void cp_commit() {
    asm volatile("cp.async.commit_group;\n");
}
template<int N>
__device__ __forceinline__ void cp_wait() {
    asm volatile("cp.async.wait_group %0;\n" :: "n"(N));
}

// ---------------- weight pre-rounding (once per launch, ~15us total) ----
__global__ __launch_bounds__(256) void round_tf32_k(
    const float* __restrict__ in, float* __restrict__ out)
{
    size_t i = ((size_t)blockIdx.x * 256 + threadIdx.x) * 4;
    float4 v = *(const float4*)(in + i);
    v.x = round_tf32(v.x); v.y = round_tf32(v.y);
    v.z = round_tf32(v.z); v.w = round_tf32(v.w);
    *(float4*)(out + i) = v;
}

// ---------------- LayerNorm (output rounded to tf32 grid) --------------
__global__ __launch_bounds__(256) void layernorm_k(
    const float* __restrict__ in, const float* __restrict__ w,
    const float* __restrict__ b, float* __restrict__ out)
{
    int row = blockIdx.x;
    int tid = threadIdx.x;
    const float* r = in + (size_t)row * DD;
    float4 v = *(const float4*)(r + tid * 4);
    float s  = v.x + v.y + v.z + v.w;
    float sq = v.x * v.x + v.y * v.y + v.z * v.z + v.w * v.w;
    #pragma unroll
    for (int o = 16; o > 0; o >>= 1) {
        s  += __shfl_xor_sync(0xffffffffu, s,  o);
        sq += __shfl_xor_sync(0xffffffffu, sq, o);
    }
    __shared__ float ss[8], ssq[8];
    int warp = tid >> 5, lane = tid & 31;
    if (lane == 0) { ss[warp] = s; ssq[warp] = sq; }
    __syncthreads();
    float ts = 0.f, tsq = 0.f;
    #pragma unroll
    for (int i = 0; i < 8; i++) { ts += ss[i]; tsq += ssq[i]; }
    float mu  = ts * (1.f / 1024.f);
    float var = tsq * (1.f / 1024.f) - mu * mu;
    float inv = rsqrtf(var + 1e-5f);
    float4 wv = *(const float4*)(w + tid * 4);
    float4 bv = *(const float4*)(b + tid * 4);
    float4 o4;
    o4.x = round_tf32((v.x - mu) * inv * wv.x + bv.x);
    o4.y = round_tf32((v.y - mu) * inv * wv.y + bv.y);
    o4.z = round_tf32((v.z - mu) * inv * wv.z + bv.z);
    o4.w = round_tf32((v.w - mu) * inv * wv.w + bv.w);
    *(float4*)(out + (size_t)row * DD + tid * 4) = o4;
}

// ---------------- tf32 tensor-core GEMM, 2-stage cp.async pipeline ------
// Inputs MUST be pre-rounded to the tf32 grid (no cvt in inner loop).
// EPI: 0 bias, 1 bias+gelu, 2 bias+residual.  RND: round stored output.
#define GPAD 36
#define GSTG (128 * GPAD)

template<int EPI, bool RND>
__global__ __launch_bounds__(256) void gemm_tc(
    const float* __restrict__ A, const float* __restrict__ Bm,
    const float* __restrict__ bias, const float* __restrict__ res,
    float* __restrict__ C, int N, int K)
{
    extern __shared__ float smem_g[];
    float* Asm = smem_g;                 // [2][128][GPAD]
    float* Bsm = smem_g + 2 * GSTG;      // [2][128][GPAD]

    int m0 = blockIdx.y << 7, n0 = blockIdx.x << 7;
    int tid = threadIdx.x;
    int warp = tid >> 5, lane = tid & 31;
    int gid = lane >> 2, tig = lane & 3;
    int wm = (warp & 3) << 5, wn = (warp >> 2) << 6;

    int lrow = tid >> 3;              // 0..31
    int lcol = (tid & 7) << 2;        // 0,4,..,28
    const float* Ag = A  + (size_t)(m0 + lrow) * K + lcol;
    const float* Bg = Bm + (size_t)(n0 + lrow) * K + lcol;

    int nt = K >> 5;

    {
        uint32_t da = (uint32_t)__cvta_generic_to_shared(Asm + lrow * GPAD + lcol);
        uint32_t db = (uint32_t)__cvta_generic_to_shared(Bsm + lrow * GPAD + lcol);
        #pragma unroll
        for (int r = 0; r < 4; r++) {
            cp_async16(da + r * 32 * GPAD * 4, Ag + (size_t)(r * 32) * K);
            cp_async16(db + r * 32 * GPAD * 4, Bg + (size_t)(r * 32) * K);
        }
        cp_commit();
    }

    float acc[2][8][4] = {};

    for (int kt = 0; kt < nt; kt++) {
        if (kt + 1 < nt) {
            int st = (kt + 1) & 1;
            uint32_t da = (uint32_t)__cvta_generic_to_shared(Asm + st * GSTG + lrow * GPAD + lcol);
            uint32_t db = (uint32_t)__cvta_generic_to_shared(Bsm + st * GSTG + lrow * GPAD + lcol);
            const float* Ags = Ag + (size_t)(kt + 1) * 32;
            const float* Bgs = Bg + (size_t)(kt + 1) * 32;
            #pragma unroll
            for (int r = 0; r < 4; r++) {
                cp_async16(da + r * 32 * GPAD * 4, Ags + (size_t)(r * 32) * K);
                cp_async16(db + r * 32 * GPAD * 4, Bgs + (size_t)(r * 32) * K);
            }
            cp_commit();
            cp_wait<1>();
        } else {
            cp_wait<0>();
        }
        __syncthreads();

        const uint32_t* As = (const uint32_t*)(Asm + (kt & 1) * GSTG);
        const uint32_t* Bs = (const uint32_t*)(Bsm + (kt & 1) * GSTG);

        #pragma unroll
        for (int ks = 0; ks < 32; ks += 8) {
            uint32_t a[2][4], b[8][2];
            #pragma unroll
            for (int mi = 0; mi < 2; mi++) {
                int m = wm + (mi << 4) + gid;
                a[mi][0] = As[m * GPAD + ks + tig];
                a[mi][1] = As[(m + 8) * GPAD + ks + tig];
                a[mi][2] = As[m * GPAD + ks + tig + 4];
                a[mi][3] = As[(m + 8) * GPAD + ks + tig + 4];
            }
            #pragma unroll
            for (int nj = 0; nj < 8; nj++) {
                int n = wn + (nj << 3) + gid;
                b[nj][0] = Bs[n * GPAD + ks + tig];
                b[nj][1] = Bs[n * GPAD + ks + tig + 4];
            }
            #pragma unroll
            for (int mi = 0; mi < 2; mi++)
                #pragma unroll
                for (int nj = 0; nj < 8; nj++)
                    mma_tf32(acc[mi][nj], a[mi][0], a[mi][1], a[mi][2], a[mi][3],
                             b[nj][0], b[nj][1]);
        }
        __syncthreads();
    }

    #pragma unroll
    for (int mi = 0; mi < 2; mi++) {
        int m = m0 + wm + (mi << 4) + gid;
        #pragma unroll
        for (int nj = 0; nj < 8; nj++) {
            int n = n0 + wn + (nj << 3) + (tig << 1);
            float2 bb = *(const float2*)(bias + n);
            float c0 = acc[mi][nj][0] + bb.x;
            float c1 = acc[mi][nj][1] + bb.y;
            float c2 = acc[mi][nj][2] + bb.x;
            float c3 = acc[mi][nj][3] + bb.y;
            if (EPI == 1) {
                c0 = gelu_exact(c0); c1 = gelu_exact(c1);
                c2 = gelu_exact(c2); c3 = gelu_exact(c3);
            } else if (EPI == 2) {
                float2 r0 = *(const float2*)(res + (size_t)m * N + n);
                float2 r1 = *(const float2*)(res + (size_t)(m + 8) * N + n);
                c0 += r0.x; c1 += r0.y; c2 += r1.x; c3 += r1.y;
            }
            if (RND) {
                c0 = round_tf32(c0); c1 = round_tf32(c1);
                c2 = round_tf32(c2); c3 = round_tf32(c3);
            }
            *(float2*)(C + (size_t)m * N + n)       = make_float2(c0, c1);
            *(float2*)(C + (size_t)(m + 8) * N + n) = make_float2(c2, c3);
        }
    }
}

#define GEMM_SMEM (4 * GSTG * (int)sizeof(float))   // 73728 bytes

// ---------------- Attention scores: edge_out = QK^T/8 + edge -----------
// qkv already tf32-rounded: raw bit copies into smem, no cvt anywhere.
__global__ __launch_bounds__(256) void attn_scores_tc(
    const float* __restrict__ qkv, const float* __restrict__ edge,
    float* __restrict__ edge_out)
{
    __shared__ uint32_t As[128][20];
    __shared__ uint32_t Bs[128][20];
    int bz = blockIdx.z;
    int batch = bz >> 4, h = bz & 15;
    int qoff = batch * QKV_N + h * HDIM;
    int koff = qoff + DD;
    int i0 = blockIdx.y << 7, j0 = blockIdx.x << 7;
    int tid = threadIdx.x;
    int warp = tid >> 5, lane = tid & 31;
    int gid = lane >> 2, tig = lane & 3;
    int wm = (warp & 3) << 5, wn = (warp >> 2) << 6;
    float acc[2][8][4] = {};
    for (int k0 = 0; k0 < HDIM; k0 += 16) {
        #pragma unroll
        for (int t = 0; t < 2; t++) {
            int idx = tid + (t << 8);
            int row = idx >> 2, c4 = (idx & 3) << 2;
            *(uint4*)&As[row][c4] = *(const uint4*)(qkv + (size_t)(i0 + row) * ROW_STRIDE + qoff + k0 + c4);
            *(uint4*)&Bs[row][c4] = *(const uint4*)(qkv + (size_t)(j0 + row) * ROW_STRIDE + koff + k0 + c4);
        }
        __syncthreads();
        #pragma unroll
        for (int ks = 0; ks < 16; ks += 8) {
            uint32_t a[2][4], b[8][2];
            #pragma unroll
            for (int mi = 0; mi < 2; mi++) {
                int m = wm + (mi << 4) + gid;
                a[mi][0] = As[m][ks + tig];
                a[mi][1] = As[m + 8][ks + tig];
                a[mi][2] = As[m][ks + tig + 4];
                a[mi][3] = As[m + 8][ks + tig + 4];
            }
            #pragma unroll
            for (int nj = 0; nj < 8; nj++) {
                int n = wn + (nj << 3) + gid;
                b[nj][0] = Bs[n][ks + tig];
                b[nj][1] = Bs[n][ks + tig + 4];
            }
            #pragma unroll
            for (int mi = 0; mi < 2; mi++)
                #pragma unroll
                for (int nj = 0; nj < 8; nj++)
                    mma_tf32(acc[mi][nj], a[mi][0], a[mi][1], a[mi][2], a[mi][3],
                             b[nj][0], b[nj][1]);
        }
        __syncthreads();
    }
    size_t base = ((size_t)bz << 20);
    #pragma unroll
    for (int mi = 0; mi < 2; mi++) {
        int ii = i0 + wm + (mi << 4) + gid;
        #pragma unroll
        for (int nj = 0; nj < 8; nj++) {
            int jj = j0 + wn + (nj << 3) + (tig << 1);
            size_t off0 = base + ((size_t)ii << 10) + jj;
            size_t off1 = base + ((size_t)(ii + 8) << 10) + jj;
            float2 e0 = *(const float2*)(edge + off0);
            float2 e1 = *(const float2*)(edge + off1);
            *(float2*)(edge_out + off0) = make_float2(acc[mi][nj][0] * 0.125f + e0.x,
                                                      acc[mi][nj][1] * 0.125f + e0.y);
            *(float2*)(edge_out + off1) = make_float2(acc[mi][nj][2] * 0.125f + e1.x,
                                                      acc[mi][nj][3] * 0.125f + e1.y);
        }
    }
}

// ---------------- Row softmax (P rounded to tf32 grid) -----------------
__global__ __launch_bounds__(128) void softmax_rows(
    const float* __restrict__ t, float* __restrict__ P)
{
    size_t row = blockIdx.x;
    const float* r = t + (row << 10);
    float* p = P + (row << 10);
    int tid = threadIdx.x;
    float4 v0 = *(const float4*)(r + tid * 8);
    float4 v1 = *(const float4*)(r + tid * 8 + 4);
    float mx = fmaxf(fmaxf(fmaxf(v0.x, v0.y), fmaxf(v0.z, v0.w)),
                     fmaxf(fmaxf(v1.x, v1.y), fmaxf(v1.z, v1.w)));
    #pragma unroll
    for (int o = 16; o > 0; o >>= 1) mx = fmaxf(mx, __shfl_xor_sync(0xffffffffu, mx, o));
    __shared__ float sm[4];
    __shared__ float sssum[4];
    int warp = tid >> 5, lane = tid & 31;
    if (lane == 0) sm[warp] = mx;
    __syncthreads();
    float m = fmaxf(fmaxf(sm[0], sm[1]), fmaxf(sm[2], sm[3]));
    float e0 = __expf(v0.x - m), e1 = __expf(v0.y - m), e2 = __expf(v0.z - m), e3 = __expf(v0.w - m);
    float e4 = __expf(v1.x - m), e5 = __expf(v1.y - m), e6 = __expf(v1.z - m), e7 = __expf(v1.w - m);
    float s = e0 + e1 + e2 + e3 + e4 + e5 + e6 + e7;
    #pragma unroll
    for (int o = 16; o > 0; o >>= 1) s += __shfl_xor_sync(0xffffffffu, s, o);
    if (lane == 0) sssum[warp] = s;
    __syncthreads();
    float tot = sssum[0] + sssum[1] + sssum[2] + sssum[3];
    float inv = 1.0f / tot;
    *(float4*)(p + tid * 8)     = make_float4(round_tf32(e0 * inv), round_tf32(e1 * inv),
                                              round_tf32(e2 * inv), round_tf32(e3 * inv));
    *(float4*)(p + tid * 8 + 4) = make_float4(round_tf32(e4 * inv), round_tf32(e5 * inv),
                                              round_tf32(e6 * inv), round_tf32(e7 * inv));
}

// ---------------- PV: inputs pre-rounded, output rounded ---------------
__global__ __launch_bounds__(256) void attn_pv_tc(
    const float* __restrict__ P, const float* __restrict__ qkv,
    float* __restrict__ out)
{
    __shared__ uint32_t As[128][36];
    __shared__ uint32_t Bs[32][72];
    int bz = blockIdx.y;
    int batch = bz >> 4, h = bz & 15;
    int voff = batch * QKV_N + 2 * DD + h * HDIM;
    int i0 = blockIdx.x << 7;
    int tid = threadIdx.x;
    int warp = tid >> 5, lane = tid & 31;
    int gid = lane >> 2, tig = lane & 3;
    int wm = warp << 4;
    float acc[8][4] = {};
    size_t pbase = ((size_t)bz << 20);
    for (int k0 = 0; k0 < LL; k0 += 32) {
        #pragma unroll
        for (int t = 0; t < 4; t++) {
            int idx = tid + (t << 8);
            int row = idx >> 3, c4 = (idx & 7) << 2;
            *(uint4*)&As[row][c4] = *(const uint4*)(P + pbase + ((size_t)(i0 + row) << 10) + k0 + c4);
        }
        #pragma unroll
        for (int t = 0; t < 2; t++) {
            int idx = tid + (t << 8);
            int row = idx >> 4, c4 = (idx & 15) << 2;
            *(uint4*)&Bs[row][c4] = *(const uint4*)(qkv + (size_t)(k0 + row) * ROW_STRIDE + voff + c4);
        }
        __syncthreads();
        #pragma unroll
        for (int ks = 0; ks < 32; ks += 8) {
            uint32_t a[4], b[8][2];
            int m = wm + gid;
            a[0] = As[m][ks + tig];
            a[1] = As[m + 8][ks + tig];
            a[2] = As[m][ks + tig + 4];
            a[3] = As[m + 8][ks + tig + 4];
            #pragma unroll
            for (int nj = 0; nj < 8; nj++) {
                int n = (nj << 3) + gid;
                b[nj][0] = Bs[ks + tig][n];
                b[nj][1] = Bs[ks + tig + 4][n];
            }
            #pragma unroll
            for (int nj = 0; nj < 8; nj++)
                mma_tf32(acc[nj], a[0], a[1], a[2], a[3], b[nj][0], b[nj][1]);
        }
        __syncthreads();
    }
    #pragma unroll
    for (int nj = 0; nj < 8; nj++) {
        int l0 = i0 + wm + gid;
        int col = h * HDIM + (nj << 3) + (tig << 1);
        int row0 = l0 * BB + batch;
        int row1 = (l0 + 8) * BB + batch;
        *(float2*)(out + (size_t)row0 * DD + col) = make_float2(round_tf32(acc[nj][0]), round_tf32(acc[nj][1]));
        *(float2*)(out + (size_t)row1 * DD + col) = make_float2(round_tf32(acc[nj][2]), round_tf32(acc[nj][3]));
    }
}

extern "C" void kernel_launch(void* const* d_in, const int* in_sizes, int n_in,
                              void* d_out, int out_size)
{
    const float* x    = (const float*)d_in[0];
    const float* edge = (const float*)d_in[1];
    const float* Wqkv = (const float*)d_in[2];
    const float* bqkv = (const float*)d_in[3];
    const float* Wo   = (const float*)d_in[4];
    const float* bo   = (const float*)d_in[5];
    const float* W1   = (const float*)d_in[6];
    const float* b1   = (const float*)d_in[7];
    const float* W2   = (const float*)d_in[8];
    const float* b2   = (const float*)d_in[9];
    const float* n1w  = (const float*)d_in[10];
    const float* n1b  = (const float*)d_in[11];
    const float* n2w  = (const float*)d_in[12];
    const float* n2b  = (const float*)d_in[13];

    float* out_x    = (float*)d_out;
    float* edge_out = out_x + (size_t)MROWS * DD;

    float *h, *qkv, *P, *attn, *x1, *h2, *ffn, *wqkv, *wo, *w1, *w2;
    cudaGetSymbolAddress((void**)&h,    g_h);
    cudaGetSymbolAddress((void**)&qkv,  g_qkv);
    cudaGetSymbolAddress((void**)&P,    g_P);
    cudaGetSymbolAddress((void**)&attn, g_attn);
    cudaGetSymbolAddress((void**)&x1,   g_x1);
    cudaGetSymbolAddress((void**)&h2,   g_h2);
    cudaGetSymbolAddress((void**)&ffn,  g_ffn);
    cudaGetSymbolAddress((void**)&wqkv, g_wqkv);
    cudaGetSymbolAddress((void**)&wo,   g_wo);
    cudaGetSymbolAddress((void**)&w1,   g_w1);
    cudaGetSymbolAddress((void**)&w2,   g_w2);

    cudaFuncSetAttribute(gemm_tc<0, true>,  cudaFuncAttributeMaxDynamicSharedMemorySize, GEMM_SMEM);
    cudaFuncSetAttribute(gemm_tc<1, true>,  cudaFuncAttributeMaxDynamicSharedMemorySize, GEMM_SMEM);
    cudaFuncSetAttribute(gemm_tc<2, false>, cudaFuncAttributeMaxDynamicSharedMemorySize, GEMM_SMEM);

    // 0) pre-round weights to tf32 grid
    round_tf32_k<<<(QKV_N * DD) / 1024, 256>>>(Wqkv, wqkv);
    round_tf32_k<<<(DD * DD) / 1024, 256>>>(Wo, wo);
    round_tf32_k<<<(DFF * DD) / 1024, 256>>>(W1, w1);
    round_tf32_k<<<(DD * DFF) / 1024, 256>>>(W2, w2);

    // 1) h = LN1(x)  (rounded)
    layernorm_k<<<MROWS, 256>>>(x, n1w, n1b, h);
    // 2) qkv = h @ Wqkv^T + bqkv  (rounded)
    gemm_tc<0, true><<<dim3(QKV_N / 128, MROWS / 128), 256, GEMM_SMEM>>>(h, wqkv, bqkv, nullptr, qkv, QKV_N, DD);
    // 3) edge_out = QK^T/8 + edge
    attn_scores_tc<<<dim3(8, 8, BHEADS), 256>>>(qkv, edge, edge_out);
    // 4) P = softmax(edge_out)  (rounded)
    softmax_rows<<<BHEADS * LL, 128>>>(edge_out, P);
    // 5) attn = P @ V  (rounded)
    attn_pv_tc<<<dim3(8, BHEADS), 256>>>(P, qkv, attn);
    // 6) x1 = x + attn @ Wo^T + bo  (exact)
    gemm_tc<2, false><<<dim3(DD / 128, MROWS / 128), 256, GEMM_SMEM>>>(attn, wo, bo, x, x1, DD, DD);
    // 7) h2 = LN2(x1)  (rounded)
    layernorm_k<<<MROWS, 256>>>(x1, n2w, n2b, h2);
    // 8) ffn = gelu(h2 @ W1^T + b1)  (rounded)
    gemm_tc<1, true><<<dim3(DFF / 128, MROWS / 128), 256, GEMM_SMEM>>>(h2, w1, b1, nullptr, ffn, DFF, DD);
    // 9) out_x = x1 + ffn @ W2^T + b2  (exact)
    gemm_tc<2, false><<<dim3(DD / 128, MROWS / 128), 256, GEMM_SMEM>>>(ffn, w2, b2, x1, out_x, DD, DFF);
}

// round 12
// speedup vs baseline: 2.8893x; 1.0175x over previous
#include <cuda_runtime.h>
#include <math.h>
#include <stdint.h>

// Problem dims
#define LL 1024
#define BB 4
#define DD 1024
#define HH 16
#define HDIM 64
#define BHEADS 64
#define DFF 4096
#define MROWS 4096            // L*B
#define QKV_N 3072            // 3*D
#define ROW_STRIDE 12288      // B*3D

// Scratch (allocation-free: __device__ globals)
__device__ float g_h   [(size_t)MROWS * DD];
__device__ float g_qkv [(size_t)MROWS * QKV_N];
__device__ float g_P   [(size_t)BHEADS * LL * LL];
__device__ float g_attn[(size_t)MROWS * DD];
__device__ float g_x1  [(size_t)MROWS * DD];
__device__ float g_h2  [(size_t)MROWS * DD];
__device__ float g_ffn [(size_t)MROWS * DFF];
// tf32-pre-rounded weight copies
__device__ float g_wqkv[(size_t)QKV_N * DD];
__device__ float g_wo  [(size_t)DD * DD];
__device__ float g_w1  [(size_t)DFF * DD];
__device__ float g_w2  [(size_t)DD * DFF];

// ---------------- helpers ----------------
__device__ __forceinline__ uint32_t f2tf32(float x) {
    uint32_t r;
    asm("cvt.rna.tf32.f32 %0, %1;" : "=r"(r) : "f"(x));
    return r;
}
__device__ __forceinline__ float round_tf32(float x) {
    return __uint_as_float(f2tf32(x));
}

__device__ __forceinline__ void mma_tf32(float c[4],
    uint32_t a0, uint32_t a1, uint32_t a2, uint32_t a3,
    uint32_t b0, uint32_t b1)
{
    asm volatile(
        "mma.sync.aligned.m16n8k8.row.col.f32.tf32.tf32.f32 "
        "{%0,%1,%2,%3}, {%4,%5,%6,%7}, {%8,%9}, {%0,%1,%2,%3};\n"
        : "+f"(c[0]), "+f"(c[1]), "+f"(c[2]), "+f"(c[3])
        : "r"(a0), "r"(a1), "r"(a2), "r"(a3), "r"(b0), "r"(b1));
}

__device__ __forceinline__ float gelu_exact(float x) {
    return 0.5f * x * (1.0f + erff(x * 0.70710678118654752f));
}

__device__ __forceinline__ void cp_async16(uint32_t smem_dst, const void* gptr) {
    asm volatile("cp.async.ca.shared.global [%0], [%1], 16;\n"
                 :: "r"(smem_dst), "l"(gptr));
}
__device__ __forceinline__ void cp_commit() {
    asm volatile("cp.async.commit_group;\n");
}
template<int N>
__device__ __forceinline__ void cp_wait() {
    asm volatile("cp.async.wait_group %0;\n" :: "n"(N));
}

// ---------------- weight pre-rounding (once per launch) ----------------
__global__ __launch_bounds__(256) void round_tf32_k(
    const float* __restrict__ in, float* __restrict__ out)
{
    size_t i = ((size_t)blockIdx.x * 256 + threadIdx.x) * 4;
    float4 v = *(const float4*)(in + i);
    v.x = round_tf32(v.x); v.y = round_tf32(v.y);
    v.z = round_tf32(v.z); v.w = round_tf32(v.w);
    *(float4*)(out + i) = v;
}

// ---------------- LayerNorm (output rounded to tf32 grid) --------------
__global__ __launch_bounds__(256) void layernorm_k(
    const float* __restrict__ in, const float* __restrict__ w,
    const float* __restrict__ b, float* __restrict__ out)
{
    int row = blockIdx.x;
    int tid = threadIdx.x;
    const float* r = in + (size_t)row * DD;
    float4 v = *(const float4*)(r + tid * 4);
    float s  = v.x + v.y + v.z + v.w;
    float sq = v.x * v.x + v.y * v.y + v.z * v.z + v.w * v.w;
    #pragma unroll
    for (int o = 16; o > 0; o >>= 1) {
        s  += __shfl_xor_sync(0xffffffffu, s,  o);
        sq += __shfl_xor_sync(0xffffffffu, sq, o);
    }
    __shared__ float ss[8], ssq[8];
    int warp = tid >> 5, lane = tid & 31;
    if (lane == 0) { ss[warp] = s; ssq[warp] = sq; }
    __syncthreads();
    float ts = 0.f, tsq = 0.f;
    #pragma unroll
    for (int i = 0; i < 8; i++) { ts += ss[i]; tsq += ssq[i]; }
    float mu  = ts * (1.f / 1024.f);
    float var = tsq * (1.f / 1024.f) - mu * mu;
    float inv = rsqrtf(var + 1e-5f);
    float4 wv = *(const float4*)(w + tid * 4);
    float4 bv = *(const float4*)(b + tid * 4);
    float4 o4;
    o4.x = round_tf32((v.x - mu) * inv * wv.x + bv.x);
    o4.y = round_tf32((v.y - mu) * inv * wv.y + bv.y);
    o4.z = round_tf32((v.z - mu) * inv * wv.z + bv.z);
    o4.w = round_tf32((v.w - mu) * inv * wv.w + bv.w);
    *(float4*)(out + (size_t)row * DD + tid * 4) = o4;
}

// ---------------- tf32 tensor-core GEMM, 2-stage cp.async pipeline ------
// BM=256, BN=128, BK=32; 8 warps (4m x 2n), warp tile 64x64.
// Inputs MUST be pre-rounded to the tf32 grid (no cvt in inner loop).
// EPI: 0 bias, 1 bias+gelu, 2 bias+residual.  RND: round stored output.
#define GPAD 36
#define ASTG (256 * GPAD)
#define BSTG (128 * GPAD)
#define GEMM_SMEM ((2 * ASTG + 2 * BSTG) * (int)sizeof(float))   // 110592 B

template<int EPI, bool RND>
__global__ __launch_bounds__(256, 1) void gemm_tc(
    const float* __restrict__ A, const float* __restrict__ Bm,
    const float* __restrict__ bias, const float* __restrict__ res,
    float* __restrict__ C, int N, int K)
{
    extern __shared__ float smem_g[];
    float* Asm = smem_g;                  // [2][256][GPAD]
    float* Bsm = smem_g + 2 * ASTG;       // [2][128][GPAD]

    int m0 = blockIdx.y << 8, n0 = blockIdx.x << 7;
    int tid = threadIdx.x;
    int warp = tid >> 5, lane = tid & 31;
    int gid = lane >> 2, tig = lane & 3;
    int wm = (warp & 3) << 6;     // 0,64,128,192
    int wn = (warp >> 2) << 6;    // 0,64

    int lrow = tid >> 3;          // 0..31
    int lcol = (tid & 7) << 2;    // 0,4,..,28
    const float* Ag = A  + (size_t)(m0 + lrow) * K + lcol;
    const float* Bg = Bm + (size_t)(n0 + lrow) * K + lcol;

    int nt = K >> 5;

    {
        uint32_t da = (uint32_t)__cvta_generic_to_shared(Asm + lrow * GPAD + lcol);
        uint32_t db = (uint32_t)__cvta_generic_to_shared(Bsm + lrow * GPAD + lcol);
        #pragma unroll
        for (int r = 0; r < 8; r++)
            cp_async16(da + r * 32 * GPAD * 4, Ag + (size_t)(r * 32) * K);
        #pragma unroll
        for (int r = 0; r < 4; r++)
            cp_async16(db + r * 32 * GPAD * 4, Bg + (size_t)(r * 32) * K);
        cp_commit();
    }

    float acc[4][8][4] = {};

    for (int kt = 0; kt < nt; kt++) {
        if (kt + 1 < nt) {
            int st = (kt + 1) & 1;
            uint32_t da = (uint32_t)__cvta_generic_to_shared(Asm + st * ASTG + lrow * GPAD + lcol);
            uint32_t db = (uint32_t)__cvta_generic_to_shared(Bsm + st * BSTG + lrow * GPAD + lcol);
            const float* Ags = Ag + (size_t)(kt + 1) * 32;
            const float* Bgs = Bg + (size_t)(kt + 1) * 32;
            #pragma unroll
            for (int r = 0; r < 8; r++)
                cp_async16(da + r * 32 * GPAD * 4, Ags + (size_t)(r * 32) * K);
            #pragma unroll
            for (int r = 0; r < 4; r++)
                cp_async16(db + r * 32 * GPAD * 4, Bgs + (size_t)(r * 32) * K);
            cp_commit();
            cp_wait<1>();
        } else {
            cp_wait<0>();
        }
        __syncthreads();

        const uint32_t* As = (const uint32_t*)(Asm + (kt & 1) * ASTG);
        const uint32_t* Bs = (const uint32_t*)(Bsm + (kt & 1) * BSTG);

        #pragma unroll
        for (int ks = 0; ks < 32; ks += 8) {
            uint32_t a[4][4], b[8][2];
            #pragma unroll
            for (int mi = 0; mi < 4; mi++) {
                int m = wm + (mi << 4) + gid;
                a[mi][0] = As[m * GPAD + ks + tig];
                a[mi][1] = As[(m + 8) * GPAD + ks + tig];
                a[mi][2] = As[m * GPAD + ks + tig + 4];
                a[mi][3] = As[(m + 8) * GPAD + ks + tig + 4];
            }
            #pragma unroll
            for (int nj = 0; nj < 8; nj++) {
                int n = wn + (nj << 3) + gid;
                b[nj][0] = Bs[n * GPAD + ks + tig];
                b[nj][1] = Bs[n * GPAD + ks + tig + 4];
            }
            #pragma unroll
            for (int mi = 0; mi < 4; mi++)
                #pragma unroll
                for (int nj = 0; nj < 8; nj++)
                    mma_tf32(acc[mi][nj], a[mi][0], a[mi][1], a[mi][2], a[mi][3],
                             b[nj][0], b[nj][1]);
        }
        __syncthreads();
    }

    #pragma unroll
    for (int mi = 0; mi < 4; mi++) {
        int m = m0 + wm + (mi << 4) + gid;
        #pragma unroll
        for (int nj = 0; nj < 8; nj++) {
            int n = n0 + wn + (nj << 3) + (tig << 1);
            float2 bb = *(const float2*)(bias + n);
            float c0 = acc[mi][nj][0] + bb.x;
            float c1 = acc[mi][nj][1] + bb.y;
            float c2 = acc[mi][nj][2] + bb.x;
            float c3 = acc[mi][nj][3] + bb.y;
            if (EPI == 1) {
                c0 = gelu_exact(c0); c1 = gelu_exact(c1);
                c2 = gelu_exact(c2); c3 = gelu_exact(c3);
            } else if (EPI == 2) {
                float2 r0 = *(const float2*)(res + (size_t)m * N + n);
                float2 r1 = *(const float2*)(res + (size_t)(m + 8) * N + n);
                c0 += r0.x; c1 += r0.y; c2 += r1.x; c3 += r1.y;
            }
            if (RND) {
                c0 = round_tf32(c0); c1 = round_tf32(c1);
                c2 = round_tf32(c2); c3 = round_tf32(c3);
            }
            *(float2*)(C + (size_t)m * N + n)       = make_float2(c0, c1);
            *(float2*)(C + (size_t)(m + 8) * N + n) = make_float2(c2, c3);
        }
    }
}

// ---------------- Attention scores: edge_out = QK^T/8 + edge -----------
__global__ __launch_bounds__(256) void attn_scores_tc(
    const float* __restrict__ qkv, const float* __restrict__ edge,
    float* __restrict__ edge_out)
{
    __shared__ uint32_t As[128][20];
    __shared__ uint32_t Bs[128][20];
    int bz = blockIdx.z;
    int batch = bz >> 4, h = bz & 15;
    int qoff = batch * QKV_N + h * HDIM;
    int koff = qoff + DD;
    int i0 = blockIdx.y << 7, j0 = blockIdx.x << 7;
    int tid = threadIdx.x;
    int warp = tid >> 5, lane = tid & 31;
    int gid = lane >> 2, tig = lane & 3;
    int wm = (warp & 3) << 5, wn = (warp >> 2) << 6;
    float acc[2][8][4] = {};
    for (int k0 = 0; k0 < HDIM; k0 += 16) {
        #pragma unroll
        for (int t = 0; t < 2; t++) {
            int idx = tid + (t << 8);
            int row = idx >> 2, c4 = (idx & 3) << 2;
            *(uint4*)&As[row][c4] = *(const uint4*)(qkv + (size_t)(i0 + row) * ROW_STRIDE + qoff + k0 + c4);
            *(uint4*)&Bs[row][c4] = *(const uint4*)(qkv + (size_t)(j0 + row) * ROW_STRIDE + koff + k0 + c4);
        }
        __syncthreads();
        #pragma unroll
        for (int ks = 0; ks < 16; ks += 8) {
            uint32_t a[2][4], b[8][2];
            #pragma unroll
            for (int mi = 0; mi < 2; mi++) {
                int m = wm + (mi << 4) + gid;
                a[mi][0] = As[m][ks + tig];
                a[mi][1] = As[m + 8][ks + tig];
                a[mi][2] = As[m][ks + tig + 4];
                a[mi][3] = As[m + 8][ks + tig + 4];
            }
            #pragma unroll
            for (int nj = 0; nj < 8; nj++) {
                int n = wn + (nj << 3) + gid;
                b[nj][0] = Bs[n][ks + tig];
                b[nj][1] = Bs[n][ks + tig + 4];
            }
            #pragma unroll
            for (int mi = 0; mi < 2; mi++)
                #pragma unroll
                for (int nj = 0; nj < 8; nj++)
                    mma_tf32(acc[mi][nj], a[mi][0], a[mi][1], a[mi][2], a[mi][3],
                             b[nj][0], b[nj][1]);
        }
        __syncthreads();
    }
    size_t base = ((size_t)bz << 20);
    #pragma unroll
    for (int mi = 0; mi < 2; mi++) {
        int ii = i0 + wm + (mi << 4) + gid;
        #pragma unroll
        for (int nj = 0; nj < 8; nj++) {
            int jj = j0 + wn + (nj << 3) + (tig << 1);
            size_t off0 = base + ((size_t)ii << 10) + jj;
            size_t off1 = base + ((size_t)(ii + 8) << 10) + jj;
            float2 e0 = *(const float2*)(edge + off0);
            float2 e1 = *(const float2*)(edge + off1);
            *(float2*)(edge_out + off0) = make_float2(acc[mi][nj][0] * 0.125f + e0.x,
                                                      acc[mi][nj][1] * 0.125f + e0.y);
            *(float2*)(edge_out + off1) = make_float2(acc[mi][nj][2] * 0.125f + e1.x,
                                                      acc[mi][nj][3] * 0.125f + e1.y);
        }
    }
}

// ---------------- Row softmax (P rounded to tf32 grid) -----------------
__global__ __launch_bounds__(128) void softmax_rows(
    const float* __restrict__ t, float* __restrict__ P)
{
    size_t row = blockIdx.x;
    const float* r = t + (row << 10);
    float* p = P + (row << 10);
    int tid = threadIdx.x;
    float4 v0 = *(const float4*)(r + tid * 8);
    float4 v1 = *(const float4*)(r + tid * 8 + 4);
    float mx = fmaxf(fmaxf(fmaxf(v0.x, v0.y), fmaxf(v0.z, v0.w)),
                     fmaxf(fmaxf(v1.x, v1.y), fmaxf(v1.z, v1.w)));
    #pragma unroll
    for (int o = 16; o > 0; o >>= 1) mx = fmaxf(mx, __shfl_xor_sync(0xffffffffu, mx, o));
    __shared__ float sm[4];
    __shared__ float sssum[4];
    int warp = tid >> 5, lane = tid & 31;
    if (lane == 0) sm[warp] = mx;
    __syncthreads();
    float m = fmaxf(fmaxf(sm[0], sm[1]), fmaxf(sm[2], sm[3]));
    float e0 = __expf(v0.x - m), e1 = __expf(v0.y - m), e2 = __expf(v0.z - m), e3 = __expf(v0.w - m);
    float e4 = __expf(v1.x - m), e5 = __expf(v1.y - m), e6 = __expf(v1.z - m), e7 = __expf(v1.w - m);
    float s = e0 + e1 + e2 + e3 + e4 + e5 + e6 + e7;
    #pragma unroll
    for (int o = 16; o > 0; o >>= 1) s += __shfl_xor_sync(0xffffffffu, s, o);
    if (lane == 0) sssum[warp] = s;
    __syncthreads();
    float tot = sssum[0] + sssum[1] + sssum[2] + sssum[3];
    float inv = 1.0f / tot;
    *(float4*)(p + tid * 8)     = make_float4(round_tf32(e0 * inv), round_tf32(e1 * inv),
                                              round_tf32(e2 * inv), round_tf32(e3 * inv));
    *(float4*)(p + tid * 8 + 4) = make_float4(round_tf32(e4 * inv), round_tf32(e5 * inv),
                                              round_tf32(e6 * inv), round_tf32(e7 * inv));
}

// ---------------- PV: inputs pre-rounded, output rounded ---------------
__global__ __launch_bounds__(256) void attn_pv_tc(
    const float* __restrict__ P, const float* __restrict__ qkv,
    float* __restrict__ out)
{
    __shared__ uint32_t As[128][36];
    __shared__ uint32_t Bs[32][72];
    int bz = blockIdx.y;
    int batch = bz >> 4, h = bz & 15;
    int voff = batch * QKV_N + 2 * DD + h * HDIM;
    int i0 = blockIdx.x << 7;
    int tid = threadIdx.x;
    int warp = tid >> 5, lane = tid & 31;
    int gid = lane >> 2, tig = lane & 3;
    int wm = warp << 4;
    float acc[8][4] = {};
    size_t pbase = ((size_t)bz << 20);
    for (int k0 = 0; k0 < LL; k0 += 32) {
        #pragma unroll
        for (int t = 0; t < 4; t++) {
            int idx = tid + (t << 8);
            int row = idx >> 3, c4 = (idx & 7) << 2;
            *(uint4*)&As[row][c4] = *(const uint4*)(P + pbase + ((size_t)(i0 + row) << 10) + k0 + c4);
        }
        #pragma unroll
        for (int t = 0; t < 2; t++) {
            int idx = tid + (t << 8);
            int row = idx >> 4, c4 = (idx & 15) << 2;
            *(uint4*)&Bs[row][c4] = *(const uint4*)(qkv + (size_t)(k0 + row) * ROW_STRIDE + voff + c4);
        }
        __syncthreads();
        #pragma unroll
        for (int ks = 0; ks < 32; ks += 8) {
            uint32_t a[4], b[8][2];
            int m = wm + gid;
            a[0] = As[m][ks + tig];
            a[1] = As[m + 8][ks + tig];
            a[2] = As[m][ks + tig + 4];
            a[3] = As[m + 8][ks + tig + 4];
            #pragma unroll
            for (int nj = 0; nj < 8; nj++) {
                int n = (nj << 3) + gid;
                b[nj][0] = Bs[ks + tig][n];
                b[nj][1] = Bs[ks + tig + 4][n];
            }
            #pragma unroll
            for (int nj = 0; nj < 8; nj++)
                mma_tf32(acc[nj], a[0], a[1], a[2], a[3], b[nj][0], b[nj][1]);
        }
        __syncthreads();
    }
    #pragma unroll
    for (int nj = 0; nj < 8; nj++) {
        int l0 = i0 + wm + gid;
        int col = h * HDIM + (nj << 3) + (tig << 1);
        int row0 = l0 * BB + batch;
        int row1 = (l0 + 8) * BB + batch;
        *(float2*)(out + (size_t)row0 * DD + col) = make_float2(round_tf32(acc[nj][0]), round_tf32(acc[nj][1]));
        *(float2*)(out + (size_t)row1 * DD + col) = make_float2(round_tf32(acc[nj][2]), round_tf32(acc[nj][3]));
    }
}

extern "C" void kernel_launch(void* const* d_in, const int* in_sizes, int n_in,
                              void* d_out, int out_size)
{
    const float* x    = (const float*)d_in[0];
    const float* edge = (const float*)d_in[1];
    const float* Wqkv = (const float*)d_in[2];
    const float* bqkv = (const float*)d_in[3];
    const float* Wo   = (const float*)d_in[4];
    const float* bo   = (const float*)d_in[5];
    const float* W1   = (const float*)d_in[6];
    const float* b1   = (const float*)d_in[7];
    const float* W2   = (const float*)d_in[8];
    const float* b2   = (const float*)d_in[9];
    const float* n1w  = (const float*)d_in[10];
    const float* n1b  = (const float*)d_in[11];
    const float* n2w  = (const float*)d_in[12];
    const float* n2b  = (const float*)d_in[13];

    float* out_x    = (float*)d_out;
    float* edge_out = out_x + (size_t)MROWS * DD;

    float *h, *qkv, *P, *attn, *x1, *h2, *ffn, *wqkv, *wo, *w1, *w2;
    cudaGetSymbolAddress((void**)&h,    g_h);
    cudaGetSymbolAddress((void**)&qkv,  g_qkv);
    cudaGetSymbolAddress((void**)&P,    g_P);
    cudaGetSymbolAddress((void**)&attn, g_attn);
    cudaGetSymbolAddress((void**)&x1,   g_x1);
    cudaGetSymbolAddress((void**)&h2,   g_h2);
    cudaGetSymbolAddress((void**)&ffn,  g_ffn);
    cudaGetSymbolAddress((void**)&wqkv, g_wqkv);
    cudaGetSymbolAddress((void**)&wo,   g_wo);
    cudaGetSymbolAddress((void**)&w1,   g_w1);
    cudaGetSymbolAddress((void**)&w2,   g_w2);

    cudaFuncSetAttribute(gemm_tc<0, true>,  cudaFuncAttributeMaxDynamicSharedMemorySize, GEMM_SMEM);
    cudaFuncSetAttribute(gemm_tc<1, true>,  cudaFuncAttributeMaxDynamicSharedMemorySize, GEMM_SMEM);
    cudaFuncSetAttribute(gemm_tc<2, false>, cudaFuncAttributeMaxDynamicSharedMemorySize, GEMM_SMEM);

    // 0) pre-round weights to tf32 grid
    round_tf32_k<<<(QKV_N * DD) / 1024, 256>>>(Wqkv, wqkv);
    round_tf32_k<<<(DD * DD) / 1024, 256>>>(Wo, wo);
    round_tf32_k<<<(DFF * DD) / 1024, 256>>>(W1, w1);
    round_tf32_k<<<(DD * DFF) / 1024, 256>>>(W2, w2);

    // 1) h = LN1(x)  (rounded)
    layernorm_k<<<MROWS, 256>>>(x, n1w, n1b, h);
    // 2) qkv = h @ Wqkv^T + bqkv  (rounded)
    gemm_tc<0, true><<<dim3(QKV_N / 128, MROWS / 256), 256, GEMM_SMEM>>>(h, wqkv, bqkv, nullptr, qkv, QKV_N, DD);
    // 3) edge_out = QK^T/8 + edge
    attn_scores_tc<<<dim3(8, 8, BHEADS), 256>>>(qkv, edge, edge_out);
    // 4) P = softmax(edge_out)  (rounded)
    softmax_rows<<<BHEADS * LL, 128>>>(edge_out, P);
    // 5) attn = P @ V  (rounded)
    attn_pv_tc<<<dim3(8, BHEADS), 256>>>(P, qkv, attn);
    // 6) x1 = x + attn @ Wo^T + bo  (exact)
    gemm_tc<2, false><<<dim3(DD / 128, MROWS / 256), 256, GEMM_SMEM>>>(attn, wo, bo, x, x1, DD, DD);
    // 7) h2 = LN2(x1)  (rounded)
    layernorm_k<<<MROWS, 256>>>(x1, n2w, n2b, h2);
    // 8) ffn = gelu(h2 @ W1^T + b1)  (rounded)
    gemm_tc<1, true><<<dim3(DFF / 128, MROWS / 256), 256, GEMM_SMEM>>>(h2, w1, b1, nullptr, ffn, DFF, DD);
    // 9) out_x = x1 + ffn @ W2^T + b2  (exact)
    gemm_tc<2, false><<<dim3(DD / 128, MROWS / 256), 256, GEMM_SMEM>>>(ffn, w2, b2, x1, out_x, DD, DFF);
}

// round 15
// speedup vs baseline: 3.4120x; 1.1809x over previous
#include <cuda_runtime.h>
#include <cuda_fp16.h>
#include <math.h>
#include <stdint.h>

// Problem dims
#define LL 1024
#define BB 4
#define DD 1024
#define HH 16
#define HDIM 64
#define BHEADS 64
#define DFF 4096
#define MROWS 4096            // L*B
#define QKV_N 3072            // 3*D
#define ROW_STRIDE 12288      // B*3D

// Scratch (allocation-free: __device__ globals)
__device__ float g_h   [(size_t)MROWS * DD];
__device__ float g_qkv [(size_t)MROWS * QKV_N];
__device__ float g_P   [(size_t)BHEADS * LL * LL];
__device__ float g_x1  [(size_t)MROWS * DD];
__device__ float g_wqkv[(size_t)QKV_N * DD];
// fp16 buffers
__device__ __half g_attn_h[(size_t)MROWS * DD];
__device__ __half g_h2_h  [(size_t)MROWS * DD];
__device__ __half g_ffn_h [(size_t)MROWS * DFF];
__device__ __half g_wo_h  [(size_t)DD * DD];
__device__ __half g_w1_h  [(size_t)DFF * DD];
__device__ __half g_w2_h  [(size_t)DD * DFF];

// ---------------- helpers ----------------
__device__ __forceinline__ uint32_t f2tf32(float x) {
    uint32_t r;
    asm("cvt.rna.tf32.f32 %0, %1;" : "=r"(r) : "f"(x));
    return r;
}
__device__ __forceinline__ float round_tf32(float x) {
    return __uint_as_float(f2tf32(x));
}

__device__ __forceinline__ void mma_tf32(float c[4],
    uint32_t a0, uint32_t a1, uint32_t a2, uint32_t a3,
    uint32_t b0, uint32_t b1)
{
    asm volatile(
        "mma.sync.aligned.m16n8k8.row.col.f32.tf32.tf32.f32 "
        "{%0,%1,%2,%3}, {%4,%5,%6,%7}, {%8,%9}, {%0,%1,%2,%3};\n"
        : "+f"(c[0]), "+f"(c[1]), "+f"(c[2]), "+f"(c[3])
        : "r"(a0), "r"(a1), "r"(a2), "r"(a3), "r"(b0), "r"(b1));
}

__device__ __forceinline__ void mma_f16(float c[4],
    uint32_t a0, uint32_t a1, uint32_t a2, uint32_t a3,
    uint32_t b0, uint32_t b1)
{
    asm volatile(
        "mma.sync.aligned.m16n8k16.row.col.f32.f16.f16.f32 "
        "{%0,%1,%2,%3}, {%4,%5,%6,%7}, {%8,%9}, {%0,%1,%2,%3};\n"
        : "+f"(c[0]), "+f"(c[1]), "+f"(c[2]), "+f"(c[3])
        : "r"(a0), "r"(a1), "r"(a2), "r"(a3), "r"(b0), "r"(b1));
}

__device__ __forceinline__ float gelu_exact(float x) {
    return 0.5f * x * (1.0f + erff(x * 0.70710678118654752f));
}

__device__ __forceinline__ void cp_async16(uint32_t smem_dst, const void* gptr) {
    asm volatile("cp.async.ca.shared.global [%0], [%1], 16;\n"
                 :: "r"(smem_dst), "l"(gptr));
}
__device__ __forceinline__ void cp_commit() {
    asm volatile("cp.async.commit_group;\n");
}
template<int N>
__device__ __forceinline__ void cp_wait() {
    asm volatile("cp.async.wait_group %0;\n" :: "n"(N));
}

// ---------------- one-time conversions ----------------
__global__ __launch_bounds__(256) void round_tf32_k(
    const float* __restrict__ in, float* __restrict__ out)
{
    size_t i = ((size_t)blockIdx.x * 256 + threadIdx.x) * 4;
    float4 v = *(const float4*)(in + i);
    v.x = round_tf32(v.x); v.y = round_tf32(v.y);
    v.z = round_tf32(v.z); v.w = round_tf32(v.w);
    *(float4*)(out + i) = v;
}

__global__ __launch_bounds__(256) void conv_f16_k(
    const float* __restrict__ in, __half* __restrict__ out)
{
    size_t i = ((size_t)blockIdx.x * 256 + threadIdx.x) * 4;
    float4 v = *(const float4*)(in + i);
    *(__half2*)(out + i)     = __floats2half2_rn(v.x, v.y);
    *(__half2*)(out + i + 2) = __floats2half2_rn(v.z, v.w);
}

// ---------------- LayerNorm variants ----------------
__global__ __launch_bounds__(256) void layernorm_k(
    const float* __restrict__ in, const float* __restrict__ w,
    const float* __restrict__ b, float* __restrict__ out)
{
    int row = blockIdx.x;
    int tid = threadIdx.x;
    const float* r = in + (size_t)row * DD;
    float4 v = *(const float4*)(r + tid * 4);
    float s  = v.x + v.y + v.z + v.w;
    float sq = v.x * v.x + v.y * v.y + v.z * v.z + v.w * v.w;
    #pragma unroll
    for (int o = 16; o > 0; o >>= 1) {
        s  += __shfl_xor_sync(0xffffffffu, s,  o);
        sq += __shfl_xor_sync(0xffffffffu, sq, o);
    }
    __shared__ float ss[8], ssq[8];
    int warp = tid >> 5, lane = tid & 31;
    if (lane == 0) { ss[warp] = s; ssq[warp] = sq; }
    __syncthreads();
    float ts = 0.f, tsq = 0.f;
    #pragma unroll
    for (int i = 0; i < 8; i++) { ts += ss[i]; tsq += ssq[i]; }
    float mu  = ts * (1.f / 1024.f);
    float var = tsq * (1.f / 1024.f) - mu * mu;
    float inv = rsqrtf(var + 1e-5f);
    float4 wv = *(const float4*)(w + tid * 4);
    float4 bv = *(const float4*)(b + tid * 4);
    float4 o4;
    o4.x = round_tf32((v.x - mu) * inv * wv.x + bv.x);
    o4.y = round_tf32((v.y - mu) * inv * wv.y + bv.y);
    o4.z = round_tf32((v.z - mu) * inv * wv.z + bv.z);
    o4.w = round_tf32((v.w - mu) * inv * wv.w + bv.w);
    *(float4*)(out + (size_t)row * DD + tid * 4) = o4;
}

__global__ __launch_bounds__(256) void layernorm_f16_k(
    const float* __restrict__ in, const float* __restrict__ w,
    const float* __restrict__ b, __half* __restrict__ out)
{
    int row = blockIdx.x;
    int tid = threadIdx.x;
    const float* r = in + (size_t)row * DD;
    float4 v = *(const float4*)(r + tid * 4);
    float s  = v.x + v.y + v.z + v.w;
    float sq = v.x * v.x + v.y * v.y + v.z * v.z + v.w * v.w;
    #pragma unroll
    for (int o = 16; o > 0; o >>= 1) {
        s  += __shfl_xor_sync(0xffffffffu, s,  o);
        sq += __shfl_xor_sync(0xffffffffu, sq, o);
    }
    __shared__ float ss[8], ssq[8];
    int warp = tid >> 5, lane = tid & 31;
    if (lane == 0) { ss[warp] = s; ssq[warp] = sq; }
    __syncthreads();
    float ts = 0.f, tsq = 0.f;
    #pragma unroll
    for (int i = 0; i < 8; i++) { ts += ss[i]; tsq += ssq[i]; }
    float mu  = ts * (1.f / 1024.f);
    float var = tsq * (1.f / 1024.f) - mu * mu;
    float inv = rsqrtf(var + 1e-5f);
    float4 wv = *(const float4*)(w + tid * 4);
    float4 bv = *(const float4*)(b + tid * 4);
    float a0 = (v.x - mu) * inv * wv.x + bv.x;
    float a1 = (v.y - mu) * inv * wv.y + bv.y;
    float a2 = (v.z - mu) * inv * wv.z + bv.z;
    float a3 = (v.w - mu) * inv * wv.w + bv.w;
    *(__half2*)(out + (size_t)row * DD + tid * 4)     = __floats2half2_rn(a0, a1);
    *(__half2*)(out + (size_t)row * DD + tid * 4 + 2) = __floats2half2_rn(a2, a3);
}

// ---------------- tf32 GEMM (QKV only), BM=256 BN=128 BK=32 ------------
#define GPAD 36
#define ASTG (256 * GPAD)
#define BSTG (128 * GPAD)
#define GEMM_SMEM ((2 * ASTG + 2 * BSTG) * (int)sizeof(float))   // 110592 B

__global__ __launch_bounds__(256, 1) void gemm_tc_qkv(
    const float* __restrict__ A, const float* __restrict__ Bm,
    const float* __restrict__ bias, float* __restrict__ C, int N, int K)
{
    extern __shared__ float smem_g[];
    float* Asm = smem_g;
    float* Bsm = smem_g + 2 * ASTG;

    int m0 = blockIdx.y << 8, n0 = blockIdx.x << 7;
    int tid = threadIdx.x;
    int warp = tid >> 5, lane = tid & 31;
    int gid = lane >> 2, tig = lane & 3;
    int wm = (warp & 3) << 6;
    int wn = (warp >> 2) << 6;

    int lrow = tid >> 3;
    int lcol = (tid & 7) << 2;
    const float* Ag = A  + (size_t)(m0 + lrow) * K + lcol;
    const float* Bg = Bm + (size_t)(n0 + lrow) * K + lcol;

    int nt = K >> 5;

    {
        uint32_t da = (uint32_t)__cvta_generic_to_shared(Asm + lrow * GPAD + lcol);
        uint32_t db = (uint32_t)__cvta_generic_to_shared(Bsm + lrow * GPAD + lcol);
        #pragma unroll
        for (int r = 0; r < 8; r++)
            cp_async16(da + r * 32 * GPAD * 4, Ag + (size_t)(r * 32) * K);
        #pragma unroll
        for (int r = 0; r < 4; r++)
            cp_async16(db + r * 32 * GPAD * 4, Bg + (size_t)(r * 32) * K);
        cp_commit();
    }

    float acc[4][8][4] = {};

    for (int kt = 0; kt < nt; kt++) {
        if (kt + 1 < nt) {
            int st = (kt + 1) & 1;
            uint32_t da = (uint32_t)__cvta_generic_to_shared(Asm + st * ASTG + lrow * GPAD + lcol);
            uint32_t db = (uint32_t)__cvta_generic_to_shared(Bsm + st * BSTG + lrow * GPAD + lcol);
            const float* Ags = Ag + (size_t)(kt + 1) * 32;
            const float* Bgs = Bg + (size_t)(kt + 1) * 32;
            #pragma unroll
            for (int r = 0; r < 8; r++)
                cp_async16(da + r * 32 * GPAD * 4, Ags + (size_t)(r * 32) * K);
            #pragma unroll
            for (int r = 0; r < 4; r++)
                cp_async16(db + r * 32 * GPAD * 4, Bgs + (size_t)(r * 32) * K);
            cp_commit();
            cp_wait<1>();
        } else {
            cp_wait<0>();
        }
        __syncthreads();

        const uint32_t* As = (const uint32_t*)(Asm + (kt & 1) * ASTG);
        const uint32_t* Bs = (const uint32_t*)(Bsm + (kt & 1) * BSTG);

        #pragma unroll
        for (int ks = 0; ks < 32; ks += 8) {
            uint32_t a[4][4], b[8][2];
            #pragma unroll
            for (int mi = 0; mi < 4; mi++) {
                int m = wm + (mi << 4) + gid;
                a[mi][0] = As[m * GPAD + ks + tig];
                a[mi][1] = As[(m + 8) * GPAD + ks + tig];
                a[mi][2] = As[m * GPAD + ks + tig + 4];
                a[mi][3] = As[(m + 8) * GPAD + ks + tig + 4];
            }
            #pragma unroll
            for (int nj = 0; nj < 8; nj++) {
                int n = wn + (nj << 3) + gid;
                b[nj][0] = Bs[n * GPAD + ks + tig];
                b[nj][1] = Bs[n * GPAD + ks + tig + 4];
            }
            #pragma unroll
            for (int mi = 0; mi < 4; mi++)
                #pragma unroll
                for (int nj = 0; nj < 8; nj++)
                    mma_tf32(acc[mi][nj], a[mi][0], a[mi][1], a[mi][2], a[mi][3],
                             b[nj][0], b[nj][1]);
        }
        __syncthreads();
    }

    #pragma unroll
    for (int mi = 0; mi < 4; mi++) {
        int m = m0 + wm + (mi << 4) + gid;
        #pragma unroll
        for (int nj = 0; nj < 8; nj++) {
            int n = n0 + wn + (nj << 3) + (tig << 1);
            float2 bb = *(const float2*)(bias + n);
            float c0 = round_tf32(acc[mi][nj][0] + bb.x);
            float c1 = round_tf32(acc[mi][nj][1] + bb.y);
            float c2 = round_tf32(acc[mi][nj][2] + bb.x);
            float c3 = round_tf32(acc[mi][nj][3] + bb.y);
            *(float2*)(C + (size_t)m * N + n)       = make_float2(c0, c1);
            *(float2*)(C + (size_t)(m + 8) * N + n) = make_float2(c2, c3);
        }
    }
}

// ---------------- fp16 GEMM: BM=128 BN=128 BK=32, m16n8k16 -------------
// A[M,K], B[N,K] fp16 (K-contiguous). EPI: 1 gelu, 2 residual.
// OUTT: 0 -> float C, 1 -> fp16 C.
#define BPAD 20   // uint32 stride (16 data + 4 pad)

template<int EPI, int OUTT>
__global__ __launch_bounds__(256) void gemm_f16k(
    const __half* __restrict__ A, const __half* __restrict__ Bm,
    const float* __restrict__ bias, const float* __restrict__ res,
    void* __restrict__ Cv, int N, int K)
{
    __shared__ uint32_t As[2][128 * BPAD];
    __shared__ uint32_t Bs[2][128 * BPAD];

    int m0 = blockIdx.y << 7, n0 = blockIdx.x << 7;
    int tid = threadIdx.x;
    int warp = tid >> 5, lane = tid & 31;
    int gid = lane >> 2, tig = lane & 3;
    int wm = (warp & 3) << 5;     // 0..96
    int wn = (warp >> 2) << 6;    // 0,64

    int lrow = tid >> 2;          // 0..63
    int lcu  = (tid & 3) << 2;    // uint32 col 0,4,8,12
    const __half* Ag = A  + (size_t)(m0 + lrow) * K + lcu * 2;
    const __half* Bg = Bm + (size_t)(n0 + lrow) * K + lcu * 2;

    int nt = K >> 5;

    {
        uint32_t da = (uint32_t)__cvta_generic_to_shared(&As[0][lrow * BPAD + lcu]);
        uint32_t db = (uint32_t)__cvta_generic_to_shared(&Bs[0][lrow * BPAD + lcu]);
        #pragma unroll
        for (int r = 0; r < 2; r++) {
            cp_async16(da + r * 64 * BPAD * 4, Ag + (size_t)(r * 64) * K);
            cp_async16(db + r * 64 * BPAD * 4, Bg + (size_t)(r * 64) * K);
        }
        cp_commit();
    }

    float acc[2][8][4] = {};

    for (int kt = 0; kt < nt; kt++) {
        if (kt + 1 < nt) {
            int st = (kt + 1) & 1;
            uint32_t da = (uint32_t)__cvta_generic_to_shared(&As[st][lrow * BPAD + lcu]);
            uint32_t db = (uint32_t)__cvta_generic_to_shared(&Bs[st][lrow * BPAD + lcu]);
            const __half* Ags = Ag + (size_t)(kt + 1) * 32;
            const __half* Bgs = Bg + (size_t)(kt + 1) * 32;
            #pragma unroll
            for (int r = 0; r < 2; r++) {
                cp_async16(da + r * 64 * BPAD * 4, Ags + (size_t)(r * 64) * K);
                cp_async16(db + r * 64 * BPAD * 4, Bgs + (size_t)(r * 64) * K);
            }
            cp_commit();
            cp_wait<1>();
        } else {
            cp_wait<0>();
        }
        __syncthreads();

        const uint32_t* Asp = As[kt & 1];
        const uint32_t* Bsp = Bs[kt & 1];

        #pragma unroll
        for (int ks = 0; ks < 16; ks += 8) {   // two k16 mma steps
            uint32_t a[2][4], b[8][2];
            #pragma unroll
            for (int mi = 0; mi < 2; mi++) {
                int m = wm + (mi << 4) + gid;
                a[mi][0] = Asp[m * BPAD + ks + tig];
                a[mi][1] = Asp[(m + 8) * BPAD + ks + tig];
                a[mi][2] = Asp[m * BPAD + ks + tig + 4];
                a[mi][3] = Asp[(m + 8) * BPAD + ks + tig + 4];
            }
            #pragma unroll
            for (int nj = 0; nj < 8; nj++) {
                int n = wn + (nj << 3) + gid;
                b[nj][0] = Bsp[n * BPAD + ks + tig];
                b[nj][1] = Bsp[n * BPAD + ks + tig + 4];
            }
            #pragma unroll
            for (int mi = 0; mi < 2; mi++)
                #pragma unroll
                for (int nj = 0; nj < 8; nj++)
                    mma_f16(acc[mi][nj], a[mi][0], a[mi][1], a[mi][2], a[mi][3],
                            b[nj][0], b[nj][1]);
        }
        __syncthreads();
    }

    #pragma unroll
    for (int mi = 0; mi < 2; mi++) {
        int m = m0 + wm + (mi << 4) + gid;
        #pragma unroll
        for (int nj = 0; nj < 8; nj++) {
            int n = n0 + wn + (nj << 3) + (tig << 1);
            float2 bb = *(const float2*)(bias + n);
            float c0 = acc[mi][nj][0] + bb.x;
            float c1 = acc[mi][nj][1] + bb.y;
            float c2 = acc[mi][nj][2] + bb.x;
            float c3 = acc[mi][nj][3] + bb.y;
            if (EPI == 1) {
                c0 = gelu_exact(c0); c1 = gelu_exact(c1);
                c2 = gelu_exact(c2); c3 = gelu_exact(c3);
            } else if (EPI == 2) {
                float2 r0 = *(const float2*)(res + (size_t)m * N + n);
                float2 r1 = *(const float2*)(res + (size_t)(m + 8) * N + n);
                c0 += r0.x; c1 += r0.y; c2 += r1.x; c3 += r1.y;
            }
            if (OUTT == 0) {
                float* C = (float*)Cv;
                *(float2*)(C + (size_t)m * N + n)       = make_float2(c0, c1);
                *(float2*)(C + (size_t)(m + 8) * N + n) = make_float2(c2, c3);
            } else {
                __half* C = (__half*)Cv;
                *(__half2*)(C + (size_t)m * N + n)       = __floats2half2_rn(c0, c1);
                *(__half2*)(C + (size_t)(m + 8) * N + n) = __floats2half2_rn(c2, c3);
            }
        }
    }
}

// ---------------- Attention scores: edge_out = QK^T/8 + edge -----------
__global__ __launch_bounds__(256) void attn_scores_tc(
    const float* __restrict__ qkv, const float* __restrict__ edge,
    float* __restrict__ edge_out)
{
    __shared__ uint32_t As[128][20];
    __shared__ uint32_t Bs[128][20];
    int bz = blockIdx.z;
    int batch = bz >> 4, h = bz & 15;
    int qoff = batch * QKV_N + h * HDIM;
    int koff = qoff + DD;
    int i0 = blockIdx.y << 7, j0 = blockIdx.x << 7;
    int tid = threadIdx.x;
    int warp = tid >> 5, lane = tid & 31;
    int gid = lane >> 2, tig = lane & 3;
    int wm = (warp & 3) << 5, wn = (warp >> 2) << 6;
    float acc[2][8][4] = {};
    for (int k0 = 0; k0 < HDIM; k0 += 16) {
        #pragma unroll
        for (int t = 0; t < 2; t++) {
            int idx = tid + (t << 8);
            int row = idx >> 2, c4 = (idx & 3) << 2;
            *(uint4*)&As[row][c4] = *(const uint4*)(qkv + (size_t)(i0 + row) * ROW_STRIDE + qoff + k0 + c4);
            *(uint4*)&Bs[row][c4] = *(const uint4*)(qkv + (size_t)(j0 + row) * ROW_STRIDE + koff + k0 + c4);
        }
        __syncthreads();
        #pragma unroll
        for (int ks = 0; ks < 16; ks += 8) {
            uint32_t a[2][4], b[8][2];
            #pragma unroll
            for (int mi = 0; mi < 2; mi++) {
                int m = wm + (mi << 4) + gid;
                a[mi][0] = As[m][ks + tig];
                a[mi][1] = As[m + 8][ks + tig];
                a[mi][2] = As[m][ks + tig + 4];
                a[mi][3] = As[m + 8][ks + tig + 4];
            }
            #pragma unroll
            for (int nj = 0; nj < 8; nj++) {
                int n = wn + (nj << 3) + gid;
                b[nj][0] = Bs[n][ks + tig];
                b[nj][1] = Bs[n][ks + tig + 4];
            }
            #pragma unroll
            for (int mi = 0; mi < 2; mi++)
                #pragma unroll
                for (int nj = 0; nj < 8; nj++)
                    mma_tf32(acc[mi][nj], a[mi][0], a[mi][1], a[mi][2], a[mi][3],
                             b[nj][0], b[nj][1]);
        }
        __syncthreads();
    }
    size_t base = ((size_t)bz << 20);
    #pragma unroll
    for (int mi = 0; mi < 2; mi++) {
        int ii = i0 + wm + (mi << 4) + gid;
        #pragma unroll
        for (int nj = 0; nj < 8; nj++) {
            int jj = j0 + wn + (nj << 3) + (tig << 1);
            size_t off0 = base + ((size_t)ii << 10) + jj;
            size_t off1 = base + ((size_t)(ii + 8) << 10) + jj;
            float2 e0 = *(const float2*)(edge + off0);
            float2 e1 = *(const float2*)(edge + off1);
            *(float2*)(edge_out + off0) = make_float2(acc[mi][nj][0] * 0.125f + e0.x,
                                                      acc[mi][nj][1] * 0.125f + e0.y);
            *(float2*)(edge_out + off1) = make_float2(acc[mi][nj][2] * 0.125f + e1.x,
                                                      acc[mi][nj][3] * 0.125f + e1.y);
        }
    }
}

// ---------------- Row softmax (P rounded to tf32 grid) -----------------
__global__ __launch_bounds__(128) void softmax_rows(
    const float* __restrict__ t, float* __restrict__ P)
{
    size_t row = blockIdx.x;
    const float* r = t + (row << 10);
    float* p = P + (row << 10);
    int tid = threadIdx.x;
    float4 v0 = *(const float4*)(r + tid * 8);
    float4 v1 = *(const float4*)(r + tid * 8 + 4);
    float mx = fmaxf(fmaxf(fmaxf(v0.x, v0.y), fmaxf(v0.z, v0.w)),
                     fmaxf(fmaxf(v1.x, v1.y), fmaxf(v1.z, v1.w)));
    #pragma unroll
    for (int o = 16; o > 0; o >>= 1) mx = fmaxf(mx, __shfl_xor_sync(0xffffffffu, mx, o));
    __shared__ float sm[4];
    __shared__ float sssum[4];
    int warp = tid >> 5, lane = tid & 31;
    if (lane == 0) sm[warp] = mx;
    __syncthreads();
    float m = fmaxf(fmaxf(sm[0], sm[1]), fmaxf(sm[2], sm[3]));
    float e0 = __expf(v0.x - m), e1 = __expf(v0.y - m), e2 = __expf(v0.z - m), e3 = __expf(v0.w - m);
    float e4 = __expf(v1.x - m), e5 = __expf(v1.y - m), e6 = __expf(v1.z - m), e7 = __expf(v1.w - m);
    float s = e0 + e1 + e2 + e3 + e4 + e5 + e6 + e7;
    #pragma unroll
    for (int o = 16; o > 0; o >>= 1) s += __shfl_xor_sync(0xffffffffu, s, o);
    if (lane == 0) sssum[warp] = s;
    __syncthreads();
    float tot = sssum[0] + sssum[1] + sssum[2] + sssum[3];
    float inv = 1.0f / tot;
    *(float4*)(p + tid * 8)     = make_float4(round_tf32(e0 * inv), round_tf32(e1 * inv),
                                              round_tf32(e2 * inv), round_tf32(e3 * inv));
    *(float4*)(p + tid * 8 + 4) = make_float4(round_tf32(e4 * inv), round_tf32(e5 * inv),
                                              round_tf32(e6 * inv), round_tf32(e7 * inv));
}

// ---------------- PV: tf32 mma, fp16 output ---------------
__global__ __launch_bounds__(256) void attn_pv_tc(
    const float* __restrict__ P, const float* __restrict__ qkv,
    __half* __restrict__ out)
{
    __shared__ uint32_t As[128][36];
    __shared__ uint32_t Bs[32][72];
    int bz = blockIdx.y;
    int batch = bz >> 4, h = bz & 15;
    int voff = batch * QKV_N + 2 * DD + h * HDIM;
    int i0 = blockIdx.x << 7;
    int tid = threadIdx.x;
    int warp = tid >> 5, lane = tid & 31;
    int gid = lane >> 2, tig = lane & 3;
    int wm = warp << 4;
    float acc[8][4] = {};
    size_t pbase = ((size_t)bz << 20);
    for (int k0 = 0; k0 < LL; k0 += 32) {
        #pragma unroll
        for (int t = 0; t < 4; t++) {
            int idx = tid + (t << 8);
            int row = idx >> 3, c4 = (idx & 7) << 2;
            *(uint4*)&As[row][c4] = *(const uint4*)(P + pbase + ((size_t)(i0 + row) << 10) + k0 + c4);
        }
        #pragma unroll
        for (int t = 0; t < 2; t++) {
            int idx = tid + (t << 8);
            int row = idx >> 4, c4 = (idx & 15) << 2;
            *(uint4*)&Bs[row][c4] = *(const uint4*)(qkv + (size_t)(k0 + row) * ROW_STRIDE + voff + c4);
        }
        __syncthreads();
        #pragma unroll
        for (int ks = 0; ks < 32; ks += 8) {
            uint32_t a[4], b[8][2];
            int m = wm + gid;
            a[0] = As[m][ks + tig];
            a[1] = As[m + 8][ks + tig];
            a[2] = As[m][ks + tig + 4];
            a[3] = As[m + 8][ks + tig + 4];
            #pragma unroll
            for (int nj = 0; nj < 8; nj++) {
                int n = (nj << 3) + gid;
                b[nj][0] = Bs[ks + tig][n];
                b[nj][1] = Bs[ks + tig + 4][n];
            }
            #pragma unroll
            for (int nj = 0; nj < 8; nj++)
                mma_tf32(acc[nj], a[0], a[1], a[2], a[3], b[nj][0], b[nj][1]);
        }
        __syncthreads();
    }
    #pragma unroll
    for (int nj = 0; nj < 8; nj++) {
        int l0 = i0 + wm + gid;
        int col = h * HDIM + (nj << 3) + (tig << 1);
        int row0 = l0 * BB + batch;
        int row1 = (l0 + 8) * BB + batch;
        *(__half2*)(out + (size_t)row0 * DD + col) = __floats2half2_rn(acc[nj][0], acc[nj][1]);
        *(__half2*)(out + (size_t)row1 * DD + col) = __floats2half2_rn(acc[nj][2], acc[nj][3]);
    }
}

extern "C" void kernel_launch(void* const* d_in, const int* in_sizes, int n_in,
                              void* d_out, int out_size)
{
    const float* x    = (const float*)d_in[0];
    const float* edge = (const float*)d_in[1];
    const float* Wqkv = (const float*)d_in[2];
    const float* bqkv = (const float*)d_in[3];
    const float* Wo   = (const float*)d_in[4];
    const float* bo   = (const float*)d_in[5];
    const float* W1   = (const float*)d_in[6];
    const float* b1   = (const float*)d_in[7];
    const float* W2   = (const float*)d_in[8];
    const float* b2   = (const float*)d_in[9];
    const float* n1w  = (const float*)d_in[10];
    const float* n1b  = (const float*)d_in[11];
    const float* n2w  = (const float*)d_in[12];
    const float* n2b  = (const float*)d_in[13];

    float* out_x    = (float*)d_out;
    float* edge_out = out_x + (size_t)MROWS * DD;

    float *h, *qkv, *P, *x1, *wqkv;
    __half *attn_h, *h2_h, *ffn_h, *wo_h, *w1_h, *w2_h;
    cudaGetSymbolAddress((void**)&h,    g_h);
    cudaGetSymbolAddress((void**)&qkv,  g_qkv);
    cudaGetSymbolAddress((void**)&P,    g_P);
    cudaGetSymbolAddress((void**)&x1,   g_x1);
    cudaGetSymbolAddress((void**)&wqkv, g_wqkv);
    cudaGetSymbolAddress((void**)&attn_h, g_attn_h);
    cudaGetSymbolAddress((void**)&h2_h,   g_h2_h);
    cudaGetSymbolAddress((void**)&ffn_h,  g_ffn_h);
    cudaGetSymbolAddress((void**)&wo_h,   g_wo_h);
    cudaGetSymbolAddress((void**)&w1_h,   g_w1_h);
    cudaGetSymbolAddress((void**)&w2_h,   g_w2_h);

    cudaFuncSetAttribute(gemm_tc_qkv, cudaFuncAttributeMaxDynamicSharedMemorySize, GEMM_SMEM);

    // 0) weight conversions
    round_tf32_k<<<(QKV_N * DD) / 1024, 256>>>(Wqkv, wqkv);
    conv_f16_k<<<(DD * DD) / 1024, 256>>>(Wo, wo_h);
    conv_f16_k<<<(DFF * DD) / 1024, 256>>>(W1, w1_h);
    conv_f16_k<<<(DD * DFF) / 1024, 256>>>(W2, w2_h);

    // 1) h = LN1(x)  (tf32-rounded)
    layernorm_k<<<MROWS, 256>>>(x, n1w, n1b, h);
    // 2) qkv = h @ Wqkv^T + bqkv  (tf32, rounded)
    gemm_tc_qkv<<<dim3(QKV_N / 128, MROWS / 256), 256, GEMM_SMEM>>>(h, wqkv, bqkv, qkv, QKV_N, DD);
    // 3) edge_out = QK^T/8 + edge  (tf32)
    attn_scores_tc<<<dim3(8, 8, BHEADS), 256>>>(qkv, edge, edge_out);
    // 4) P = softmax(edge_out)
    softmax_rows<<<BHEADS * LL, 128>>>(edge_out, P);
    // 5) attn = P @ V  (tf32 -> fp16)
    attn_pv_tc<<<dim3(8, BHEADS), 256>>>(P, qkv, attn_h);
    // 6) x1 = x + attn @ Wo^T + bo  (fp16 mma, fp32 out)
    gemm_f16k<2, 0><<<dim3(DD / 128, MROWS / 128), 256>>>(attn_h, wo_h, bo, x, x1, DD, DD);
    // 7) h2 = LN2(x1)  (fp16 out)
    layernorm_f16_k<<<MROWS, 256>>>(x1, n2w, n2b, h2_h);
    // 8) ffn = gelu(h2 @ W1^T + b1)  (fp16 mma, fp16 out)
    gemm_f16k<1, 1><<<dim3(DFF / 128, MROWS / 128), 256>>>(h2_h, w1_h, b1, nullptr, ffn_h, DFF, DD);
    // 9) out_x = x1 + ffn @ W2^T + b2  (fp16 mma, fp32 out)
    gemm_f16k<2, 0><<<dim3(DD / 128, MROWS / 128), 256>>>(ffn_h, w2_h, b2, x1, out_x, DD, DFF);
}

// round 17
// speedup vs baseline: 4.0822x; 1.1964x over previous
#include <cuda_runtime.h>
#include <cuda_fp16.h>
#include <math.h>
#include <stdint.h>

// Problem dims
#define LL 1024
#define BB 4
#define DD 1024
#define HH 16
#define HDIM 64
#define BHEADS 64
#define DFF 4096
#define MROWS 4096            // L*B
#define QKV_N 3072            // 3*D
#define RS_H 12288            // B*3D in halves

// Scratch (allocation-free: __device__ globals)
__device__ float g_x1  [(size_t)MROWS * DD];
// fp16 buffers
__device__ __half g_h_h   [(size_t)MROWS * DD];
__device__ __half g_qkv_h [(size_t)MROWS * QKV_N];
__device__ __half g_P_h   [(size_t)BHEADS * LL * LL];
__device__ __half g_attn_h[(size_t)MROWS * DD];
__device__ __half g_h2_h  [(size_t)MROWS * DD];
__device__ __half g_ffn_h [(size_t)MROWS * DFF];
__device__ __half g_wqkv_h[(size_t)QKV_N * DD];
__device__ __half g_wo_h  [(size_t)DD * DD];
__device__ __half g_w1_h  [(size_t)DFF * DD];
__device__ __half g_w2_h  [(size_t)DD * DFF];

// ---------------- helpers ----------------
__device__ __forceinline__ void mma_tf32(float c[4],
    uint32_t a0, uint32_t a1, uint32_t a2, uint32_t a3,
    uint32_t b0, uint32_t b1)
{
    asm volatile(
        "mma.sync.aligned.m16n8k8.row.col.f32.tf32.tf32.f32 "
        "{%0,%1,%2,%3}, {%4,%5,%6,%7}, {%8,%9}, {%0,%1,%2,%3};\n"
        : "+f"(c[0]), "+f"(c[1]), "+f"(c[2]), "+f"(c[3])
        : "r"(a0), "r"(a1), "r"(a2), "r"(a3), "r"(b0), "r"(b1));
}

__device__ __forceinline__ void mma_f16(float c[4],
    uint32_t a0, uint32_t a1, uint32_t a2, uint32_t a3,
    uint32_t b0, uint32_t b1)
{
    asm volatile(
        "mma.sync.aligned.m16n8k16.row.col.f32.f16.f16.f32 "
        "{%0,%1,%2,%3}, {%4,%5,%6,%7}, {%8,%9}, {%0,%1,%2,%3};\n"
        : "+f"(c[0]), "+f"(c[1]), "+f"(c[2]), "+f"(c[3])
        : "r"(a0), "r"(a1), "r"(a2), "r"(a3), "r"(b0), "r"(b1));
}

__device__ __forceinline__ float gelu_exact(float x) {
    return 0.5f * x * (1.0f + erff(x * 0.70710678118654752f));
}

__device__ __forceinline__ void cp_async16(uint32_t smem_dst, const void* gptr) {
    asm volatile("cp.async.ca.shared.global [%0], [%1], 16;\n"
                 :: "r"(smem_dst), "l"(gptr));
}
__device__ __forceinline__ void cp_commit() {
    asm volatile("cp.async.commit_group;\n");
}
template<int N>
__device__ __forceinline__ void cp_wait() {
    asm volatile("cp.async.wait_group %0;\n" :: "n"(N));
}

// ---------------- one-time weight conversion ----------------
__global__ __launch_bounds__(256) void conv_f16_k(
    const float* __restrict__ in, __half* __restrict__ out)
{
    size_t i = ((size_t)blockIdx.x * 256 + threadIdx.x) * 4;
    float4 v = *(const float4*)(in + i);
    *(__half2*)(out + i)     = __floats2half2_rn(v.x, v.y);
    *(__half2*)(out + i + 2) = __floats2half2_rn(v.z, v.w);
}

// ---------------- LayerNorm -> fp16 ----------------
__global__ __launch_bounds__(256) void layernorm_f16_k(
    const float* __restrict__ in, const float* __restrict__ w,
    const float* __restrict__ b, __half* __restrict__ out)
{
    int row = blockIdx.x;
    int tid = threadIdx.x;
    const float* r = in + (size_t)row * DD;
    float4 v = *(const float4*)(r + tid * 4);
    float s  = v.x + v.y + v.z + v.w;
    float sq = v.x * v.x + v.y * v.y + v.z * v.z + v.w * v.w;
    #pragma unroll
    for (int o = 16; o > 0; o >>= 1) {
        s  += __shfl_xor_sync(0xffffffffu, s,  o);
        sq += __shfl_xor_sync(0xffffffffu, sq, o);
    }
    __shared__ float ss[8], ssq[8];
    int warp = tid >> 5, lane = tid & 31;
    if (lane == 0) { ss[warp] = s; ssq[warp] = sq; }
    __syncthreads();
    float ts = 0.f, tsq = 0.f;
    #pragma unroll
    for (int i = 0; i < 8; i++) { ts += ss[i]; tsq += ssq[i]; }
    float mu  = ts * (1.f / 1024.f);
    float var = tsq * (1.f / 1024.f) - mu * mu;
    float inv = rsqrtf(var + 1e-5f);
    float4 wv = *(const float4*)(w + tid * 4);
    float4 bv = *(const float4*)(b + tid * 4);
    float a0 = (v.x - mu) * inv * wv.x + bv.x;
    float a1 = (v.y - mu) * inv * wv.y + bv.y;
    float a2 = (v.z - mu) * inv * wv.z + bv.z;
    float a3 = (v.w - mu) * inv * wv.w + bv.w;
    *(__half2*)(out + (size_t)row * DD + tid * 4)     = __floats2half2_rn(a0, a1);
    *(__half2*)(out + (size_t)row * DD + tid * 4 + 2) = __floats2half2_rn(a2, a3);
}

// ---------------- fp16 GEMM: BM=128 BN=128 BK=32, m16n8k16 -------------
// A[M,K], B[N,K] fp16 (K-contiguous). EPI: 0 bias, 1 gelu, 2 residual.
// OUTT: 0 -> float C, 1 -> fp16 C.
#define BPAD 20   // uint32 stride (16 data + 4 pad)

template<int EPI, int OUTT>
__global__ __launch_bounds__(256) void gemm_f16k(
    const __half* __restrict__ A, const __half* __restrict__ Bm,
    const float* __restrict__ bias, const float* __restrict__ res,
    void* __restrict__ Cv, int N, int K)
{
    __shared__ uint32_t As[2][128 * BPAD];
    __shared__ uint32_t Bs[2][128 * BPAD];

    int m0 = blockIdx.y << 7, n0 = blockIdx.x << 7;
    int tid = threadIdx.x;
    int warp = tid >> 5, lane = tid & 31;
    int gid = lane >> 2, tig = lane & 3;
    int wm = (warp & 3) << 5;     // 0..96
    int wn = (warp >> 2) << 6;    // 0,64

    int lrow = tid >> 2;          // 0..63
    int lcu  = (tid & 3) << 2;    // uint32 col 0,4,8,12
    const __half* Ag = A  + (size_t)(m0 + lrow) * K + lcu * 2;
    const __half* Bg = Bm + (size_t)(n0 + lrow) * K + lcu * 2;

    int nt = K >> 5;

    {
        uint32_t da = (uint32_t)__cvta_generic_to_shared(&As[0][lrow * BPAD + lcu]);
        uint32_t db = (uint32_t)__cvta_generic_to_shared(&Bs[0][lrow * BPAD + lcu]);
        #pragma unroll
        for (int r = 0; r < 2; r++) {
            cp_async16(da + r * 64 * BPAD * 4, Ag + (size_t)(r * 64) * K);
            cp_async16(db + r * 64 * BPAD * 4, Bg + (size_t)(r * 64) * K);
        }
        cp_commit();
    }

    float acc[2][8][4] = {};

    for (int kt = 0; kt < nt; kt++) {
        if (kt + 1 < nt) {
            int st = (kt + 1) & 1;
            uint32_t da = (uint32_t)__cvta_generic_to_shared(&As[st][lrow * BPAD + lcu]);
            uint32_t db = (uint32_t)__cvta_generic_to_shared(&Bs[st][lrow * BPAD + lcu]);
            const __half* Ags = Ag + (size_t)(kt + 1) * 32;
            const __half* Bgs = Bg + (size_t)(kt + 1) * 32;
            #pragma unroll
            for (int r = 0; r < 2; r++) {
                cp_async16(da + r * 64 * BPAD * 4, Ags + (size_t)(r * 64) * K);
                cp_async16(db + r * 64 * BPAD * 4, Bgs + (size_t)(r * 64) * K);
            }
            cp_commit();
            cp_wait<1>();
        } else {
            cp_wait<0>();
        }
        __syncthreads();

        const uint32_t* Asp = As[kt & 1];
        const uint32_t* Bsp = Bs[kt & 1];

        #pragma unroll
        for (int ks = 0; ks < 16; ks += 8) {   // two k16 mma steps
            uint32_t a[2][4], b[8][2];
            #pragma unroll
            for (int mi = 0; mi < 2; mi++) {
                int m = wm + (mi << 4) + gid;
                a[mi][0] = Asp[m * BPAD + ks + tig];
                a[mi][1] = Asp[(m + 8) * BPAD + ks + tig];
                a[mi][2] = Asp[m * BPAD + ks + tig + 4];
                a[mi][3] = Asp[(m + 8) * BPAD + ks + tig + 4];
            }
            #pragma unroll
            for (int nj = 0; nj < 8; nj++) {
                int n = wn + (nj << 3) + gid;
                b[nj][0] = Bsp[n * BPAD + ks + tig];
                b[nj][1] = Bsp[n * BPAD + ks + tig + 4];
            }
            #pragma unroll
            for (int mi = 0; mi < 2; mi++)
                #pragma unroll
                for (int nj = 0; nj < 8; nj++)
                    mma_f16(acc[mi][nj], a[mi][0], a[mi][1], a[mi][2], a[mi][3],
                            b[nj][0], b[nj][1]);
        }
        __syncthreads();
    }

    #pragma unroll
    for (int mi = 0; mi < 2; mi++) {
        int m = m0 + wm + (mi << 4) + gid;
        #pragma unroll
        for (int nj = 0; nj < 8; nj++) {
            int n = n0 + wn + (nj << 3) + (tig << 1);
            float2 bb = *(const float2*)(bias + n);
            float c0 = acc[mi][nj][0] + bb.x;
            float c1 = acc[mi][nj][1] + bb.y;
            float c2 = acc[mi][nj][2] + bb.x;
            float c3 = acc[mi][nj][3] + bb.y;
            if (EPI == 1) {
                c0 = gelu_exact(c0); c1 = gelu_exact(c1);
                c2 = gelu_exact(c2); c3 = gelu_exact(c3);
            } else if (EPI == 2) {
                float2 r0 = *(const float2*)(res + (size_t)m * N + n);
                float2 r1 = *(const float2*)(res + (size_t)(m + 8) * N + n);
                c0 += r0.x; c1 += r0.y; c2 += r1.x; c3 += r1.y;
            }
            if (OUTT == 0) {
                float* C = (float*)Cv;
                *(float2*)(C + (size_t)m * N + n)       = make_float2(c0, c1);
                *(float2*)(C + (size_t)(m + 8) * N + n) = make_float2(c2, c3);
            } else {
                __half* C = (__half*)Cv;
                *(__half2*)(C + (size_t)m * N + n)       = __floats2half2_rn(c0, c1);
                *(__half2*)(C + (size_t)(m + 8) * N + n) = __floats2half2_rn(c2, c3);
            }
        }
    }
}

// ---------------- Attention scores (fp16 mma): edge_out = QK^T/8 + edge
// 128x128 tile, K=64 halves (32 u32). Q,K from fp16 qkv.
__global__ __launch_bounds__(256) void attn_scores_f16(
    const __half* __restrict__ qkv, const float* __restrict__ edge,
    float* __restrict__ edge_out)
{
    __shared__ uint32_t As[128][36];
    __shared__ uint32_t Bs[128][36];
    int bz = blockIdx.z;
    int batch = bz >> 4, h = bz & 15;
    size_t qoff = (size_t)batch * QKV_N + h * HDIM;   // halves
    size_t koff = qoff + DD;
    int i0 = blockIdx.y << 7, j0 = blockIdx.x << 7;
    int tid = threadIdx.x;
    int warp = tid >> 5, lane = tid & 31;
    int gid = lane >> 2, tig = lane & 3;
    int wm = (warp & 3) << 5, wn = (warp >> 2) << 6;

    // fill: 128 rows x 8 uint4-chunks (64 halves) per matrix
    #pragma unroll
    for (int t = 0; t < 4; t++) {
        int idx = tid + (t << 8);
        int row = idx >> 3;
        int c = (idx & 7) << 2;           // u32 col
        *(uint4*)&As[row][c] = *(const uint4*)(qkv + (size_t)(i0 + row) * RS_H + qoff + c * 2);
        *(uint4*)&Bs[row][c] = *(const uint4*)(qkv + (size_t)(j0 + row) * RS_H + koff + c * 2);
    }
    __syncthreads();

    float acc[2][8][4] = {};
    #pragma unroll
    for (int ks = 0; ks < 32; ks += 8) {   // 4 k16 steps
        uint32_t a[2][4], b[8][2];
        #pragma unroll
        for (int mi = 0; mi < 2; mi++) {
            int m = wm + (mi << 4) + gid;
            a[mi][0] = As[m][ks + tig];
            a[mi][1] = As[m + 8][ks + tig];
            a[mi][2] = As[m][ks + tig + 4];
            a[mi][3] = As[m + 8][ks + tig + 4];
        }
        #pragma unroll
        for (int nj = 0; nj < 8; nj++) {
            int n = wn + (nj << 3) + gid;
            b[nj][0] = Bs[n][ks + tig];
            b[nj][1] = Bs[n][ks + tig + 4];
        }
        #pragma unroll
        for (int mi = 0; mi < 2; mi++)
            #pragma unroll
            for (int nj = 0; nj < 8; nj++)
                mma_f16(acc[mi][nj], a[mi][0], a[mi][1], a[mi][2], a[mi][3],
                        b[nj][0], b[nj][1]);
    }

    size_t base = ((size_t)bz << 20);
    #pragma unroll
    for (int mi = 0; mi < 2; mi++) {
        int ii = i0 + wm + (mi << 4) + gid;
        #pragma unroll
        for (int nj = 0; nj < 8; nj++) {
            int jj = j0 + wn + (nj << 3) + (tig << 1);
            size_t off0 = base + ((size_t)ii << 10) + jj;
            size_t off1 = base + ((size_t)(ii + 8) << 10) + jj;
            float2 e0 = *(const float2*)(edge + off0);
            float2 e1 = *(const float2*)(edge + off1);
            *(float2*)(edge_out + off0) = make_float2(acc[mi][nj][0] * 0.125f + e0.x,
                                                      acc[mi][nj][1] * 0.125f + e0.y);
            *(float2*)(edge_out + off1) = make_float2(acc[mi][nj][2] * 0.125f + e1.x,
                                                      acc[mi][nj][3] * 0.125f + e1.y);
        }
    }
}

// ---------------- Row softmax -> fp16 P -----------------
__global__ __launch_bounds__(128) void softmax_rows_h(
    const float* __restrict__ t, __half* __restrict__ P)
{
    size_t row = blockIdx.x;
    const float* r = t + (row << 10);
    __half* p = P + (row << 10);
    int tid = threadIdx.x;
    float4 v0 = *(const float4*)(r + tid * 8);
    float4 v1 = *(const float4*)(r + tid * 8 + 4);
    float mx = fmaxf(fmaxf(fmaxf(v0.x, v0.y), fmaxf(v0.z, v0.w)),
                     fmaxf(fmaxf(v1.x, v1.y), fmaxf(v1.z, v1.w)));
    #pragma unroll
    for (int o = 16; o > 0; o >>= 1) mx = fmaxf(mx, __shfl_xor_sync(0xffffffffu, mx, o));
    __shared__ float sm[4];
    __shared__ float sssum[4];
    int warp = tid >> 5, lane = tid & 31;
    if (lane == 0) sm[warp] = mx;
    __syncthreads();
    float m = fmaxf(fmaxf(sm[0], sm[1]), fmaxf(sm[2], sm[3]));
    float e0 = __expf(v0.x - m), e1 = __expf(v0.y - m), e2 = __expf(v0.z - m), e3 = __expf(v0.w - m);
    float e4 = __expf(v1.x - m), e5 = __expf(v1.y - m), e6 = __expf(v1.z - m), e7 = __expf(v1.w - m);
    float s = e0 + e1 + e2 + e3 + e4 + e5 + e6 + e7;
    #pragma unroll
    for (int o = 16; o > 0; o >>= 1) s += __shfl_xor_sync(0xffffffffu, s, o);
    if (lane == 0) sssum[warp] = s;
    __syncthreads();
    float tot = sssum[0] + sssum[1] + sssum[2] + sssum[3];
    float inv = 1.0f / tot;
    *(__half2*)(p + tid * 8)     = __floats2half2_rn(e0 * inv, e1 * inv);
    *(__half2*)(p + tid * 8 + 2) = __floats2half2_rn(e2 * inv, e3 * inv);
    *(__half2*)(p + tid * 8 + 4) = __floats2half2_rn(e4 * inv, e5 * inv);
    *(__half2*)(p + tid * 8 + 6) = __floats2half2_rn(e6 * inv, e7 * inv);
}

// ---------------- PV: fp16 inputs, tf32 mma (fp16 values are tf32-exact)
__global__ __launch_bounds__(256) void attn_pv_tc(
    const __half* __restrict__ P, const __half* __restrict__ qkv,
    __half* __restrict__ out)
{
    __shared__ uint32_t As[128][36];
    __shared__ uint32_t Bs[32][72];
    int bz = blockIdx.y;
    int batch = bz >> 4, h = bz & 15;
    size_t voff = (size_t)batch * QKV_N + 2 * DD + h * HDIM;
    int i0 = blockIdx.x << 7;
    int tid = threadIdx.x;
    int warp = tid >> 5, lane = tid & 31;
    int gid = lane >> 2, tig = lane & 3;
    int wm = warp << 4;
    float acc[8][4] = {};
    size_t pbase = ((size_t)bz << 20);
    for (int k0 = 0; k0 < LL; k0 += 32) {
        // A fill: P fp16 -> fp32 smem. 128 rows x 32 halves = 512 uint4; 2/thread
        #pragma unroll
        for (int t = 0; t < 2; t++) {
            int idx = tid + (t << 8);
            int row = idx >> 2;
            int c8 = (idx & 3) << 3;      // half col 0,8,16,24
            uint4 v = *(const uint4*)(P + pbase + ((size_t)(i0 + row) << 10) + k0 + c8);
            const __half2* hp = (const __half2*)&v;
            float2 f0 = __half22float2(hp[0]);
            float2 f1 = __half22float2(hp[1]);
            float2 f2 = __half22float2(hp[2]);
            float2 f3 = __half22float2(hp[3]);
            float* dst = (float*)&As[row][c8];
            dst[0] = f0.x; dst[1] = f0.y; dst[2] = f1.x; dst[3] = f1.y;
            dst[4] = f2.x; dst[5] = f2.y; dst[6] = f3.x; dst[7] = f3.y;
        }
        // B fill: V fp16 -> fp32 smem. 32 rows x 64 halves = 256 uint4; 1/thread
        {
            int row = tid >> 3;
            int c8 = (tid & 7) << 3;
            uint4 v = *(const uint4*)(qkv + (size_t)(k0 + row) * RS_H + voff + c8);
            const __half2* hp = (const __half2*)&v;
            float2 f0 = __half22float2(hp[0]);
            float2 f1 = __half22float2(hp[1]);
            float2 f2 = __half22float2(hp[2]);
            float2 f3 = __half22float2(hp[3]);
            float* dst = (float*)&Bs[row][c8];
            dst[0] = f0.x; dst[1] = f0.y; dst[2] = f1.x; dst[3] = f1.y;
            dst[4] = f2.x; dst[5] = f2.y; dst[6] = f3.x; dst[7] = f3.y;
        }
        __syncthreads();
        #pragma unroll
        for (int ks = 0; ks < 32; ks += 8) {
            uint32_t a[4], b[8][2];
            int m = wm + gid;
            a[0] = As[m][ks + tig];
            a[1] = As[m + 8][ks + tig];
            a[2] = As[m][ks + tig + 4];
            a[3] = As[m + 8][ks + tig + 4];
            #pragma unroll
            for (int nj = 0; nj < 8; nj++) {
                int n = (nj << 3) + gid;
                b[nj][0] = Bs[ks + tig][n];
                b[nj][1] = Bs[ks + tig + 4][n];
            }
            #pragma unroll
            for (int nj = 0; nj < 8; nj++)
                mma_tf32(acc[nj], a[0], a[1], a[2], a[3], b[nj][0], b[nj][1]);
        }
        __syncthreads();
    }
    #pragma unroll
    for (int nj = 0; nj < 8; nj++) {
        int l0 = i0 + wm + gid;
        int col = h * HDIM + (nj << 3) + (tig << 1);
        int row0 = l0 * BB + batch;
        int row1 = (l0 + 8) * BB + batch;
        *(__half2*)(out + (size_t)row0 * DD + col) = __floats2half2_rn(acc[nj][0], acc[nj][1]);
        *(__half2*)(out + (size_t)row1 * DD + col) = __floats2half2_rn(acc[nj][2], acc[nj][3]);
    }
}

extern "C" void kernel_launch(void* const* d_in, const int* in_sizes, int n_in,
                              void* d_out, int out_size)
{
    const float* x    = (const float*)d_in[0];
    const float* edge = (const float*)d_in[1];
    const float* Wqkv = (const float*)d_in[2];
    const float* bqkv = (const float*)d_in[3];
    const float* Wo   = (const float*)d_in[4];
    const float* bo   = (const float*)d_in[5];
    const float* W1   = (const float*)d_in[6];
    const float* b1   = (const float*)d_in[7];
    const float* W2   = (const float*)d_in[8];
    const float* b2   = (const float*)d_in[9];
    const float* n1w  = (const float*)d_in[10];
    const float* n1b  = (const float*)d_in[11];
    const float* n2w  = (const float*)d_in[12];
    const float* n2b  = (const float*)d_in[13];

    float* out_x    = (float*)d_out;
    float* edge_out = out_x + (size_t)MROWS * DD;

    float *x1;
    __half *h_h, *qkv_h, *P_h, *attn_h, *h2_h, *ffn_h, *wqkv_h, *wo_h, *w1_h, *w2_h;
    cudaGetSymbolAddress((void**)&x1,     g_x1);
    cudaGetSymbolAddress((void**)&h_h,    g_h_h);
    cudaGetSymbolAddress((void**)&qkv_h,  g_qkv_h);
    cudaGetSymbolAddress((void**)&P_h,    g_P_h);
    cudaGetSymbolAddress((void**)&attn_h, g_attn_h);
    cudaGetSymbolAddress((void**)&h2_h,   g_h2_h);
    cudaGetSymbolAddress((void**)&ffn_h,  g_ffn_h);
    cudaGetSymbolAddress((void**)&wqkv_h, g_wqkv_h);
    cudaGetSymbolAddress((void**)&wo_h,   g_wo_h);
    cudaGetSymbolAddress((void**)&w1_h,   g_w1_h);
    cudaGetSymbolAddress((void**)&w2_h,   g_w2_h);

    // 0) weight conversions to fp16
    conv_f16_k<<<(QKV_N * DD) / 1024, 256>>>(Wqkv, wqkv_h);
    conv_f16_k<<<(DD * DD) / 1024, 256>>>(Wo, wo_h);
    conv_f16_k<<<(DFF * DD) / 1024, 256>>>(W1, w1_h);
    conv_f16_k<<<(DD * DFF) / 1024, 256>>>(W2, w2_h);

    // 1) h = LN1(x)  (fp16)
    layernorm_f16_k<<<MROWS, 256>>>(x, n1w, n1b, h_h);
    // 2) qkv = h @ Wqkv^T + bqkv  (fp16 mma, fp16 out)
    gemm_f16k<0, 1><<<dim3(QKV_N / 128, MROWS / 128), 256>>>(h_h, wqkv_h, bqkv, nullptr, qkv_h, QKV_N, DD);
    // 3) edge_out = QK^T/8 + edge  (fp16 mma, fp32 out)
    attn_scores_f16<<<dim3(8, 8, BHEADS), 256>>>(qkv_h, edge, edge_out);
    // 4) P = softmax(edge_out)  (fp16 out)
    softmax_rows_h<<<BHEADS * LL, 128>>>(edge_out, P_h);
    // 5) attn = P @ V  (tf32 mma on fp16-exact values, fp16 out)
    attn_pv_tc<<<dim3(8, BHEADS), 256>>>(P_h, qkv_h, attn_h);
    // 6) x1 = x + attn @ Wo^T + bo  (fp16 mma, fp32 out)
    gemm_f16k<2, 0><<<dim3(DD / 128, MROWS / 128), 256>>>(attn_h, wo_h, bo, x, x1, DD, DD);
    // 7) h2 = LN2(x1)  (fp16 out)
    layernorm_f16_k<<<MROWS, 256>>>(x1, n2w, n2b, h2_h);
    // 8) ffn = gelu(h2 @ W1^T + b1)  (fp16 mma, fp16 out)
    gemm_f16k<1, 1><<<dim3(DFF / 128, MROWS / 128), 256>>>(h2_h, w1_h, b1, nullptr, ffn_h, DFF, DD);
    // 9) out_x = x1 + ffn @ W2^T + b2  (fp16 mma, fp32 out)
    gemm_f16k<2, 0><<<dim3(DD / 128, MROWS / 128), 256>>>(ffn_h, w2_h, b2, x1, out_x, DD, DFF);
}